// round 10
// baseline (speedup 1.0000x reference)
#include <cuda_runtime.h>

#define NB 64
#define NP 1024
#define CF 16
#define KK 16
#define BN_EPS 1e-5f

typedef unsigned int u32;
typedef unsigned long long u64;

#define FMA2(d, a, b, c) \
    asm("fma.rn.f32x2 %0, %1, %2, %3;" : "=l"(d) : "l"(a), "l"(b), "l"(c))
#define UNPACK2(lo, hi, v) \
    asm("mov.b64 {%0, %1}, %2;" : "=f"(lo), "=f"(hi) : "l"(v))
#define PACK2D(d, lo, hi) \
    asm("mov.b64 %0, {%1, %2};" : "=l"(d) : "f"(lo), "f"(hi))

__device__ __forceinline__ u64 dupf(float x){
    u32 b = __float_as_uint(x);
    return ((u64)b << 32) | (u64)b;
}

// ---------------- static scratch (no allocations allowed) ----------------
__device__ float g_C [NB*NP*64];
__device__ float g_Y [NB*NP*64];
__device__ float g_SC[NB*NP*64];
__device__ int   g_idx[NB*NP*KK];
__device__ int   g_valid[NB];
__device__ u64   g_W1d[64*64];     // W1 (BN-scaled), transposed [c][o], DUPLICATED (w,w)
__device__ u64   g_W2d[64*64];
__device__ u64   g_t1d[64], g_t2d[64];   // duplicated bias pairs
__device__ float g_W0at[CF*64], g_W0bt[CF*64], g_Wst[CF*64];
__device__ float g_t0[64], g_ts[64];

// ---------------- fold BN into weights / biases ----------------
__global__ void fold_kernel(const float* __restrict__ W0, const float* __restrict__ W1,
    const float* __restrict__ W2, const float* __restrict__ Ws,
    const float* g0,const float* b0,const float* m0,const float* v0,
    const float* g1,const float* b1,const float* m1,const float* v1,
    const float* g2,const float* b2,const float* m2,const float* v2,
    const float* gs,const float* bs,const float* ms,const float* vs)
{
    int t = blockIdx.x*blockDim.x + threadIdx.x;
    if (t < 64){
        float s0 = g0[t]*rsqrtf(v0[t]+BN_EPS); g_t0[t]=b0[t]-m0[t]*s0;
        float s1 = g1[t]*rsqrtf(v1[t]+BN_EPS); g_t1d[t]=dupf(b1[t]-m1[t]*s1);
        float s2 = g2[t]*rsqrtf(v2[t]+BN_EPS); g_t2d[t]=dupf(b2[t]-m2[t]*s2);
        float ss = gs[t]*rsqrtf(vs[t]+BN_EPS); g_ts[t]=bs[t]-ms[t]*ss;
    }
    if (t < 1024){
        int o = t >> 4, c = t & 15;
        float s0 = g0[o]*rsqrtf(v0[o]+BN_EPS);
        float ss = gs[o]*rsqrtf(vs[o]+BN_EPS);
        float wa = W0[o*32 + c], wb = W0[o*32 + 16 + c];
        g_W0at[c*64 + o] = (wa + wb)*s0;
        g_W0bt[c*64 + o] = wb*s0;
        g_Wst [c*64 + o] = Ws[o*16 + c]*ss;
    }
    if (t < 4096){
        int oo = t >> 6, cc = t & 63;
        g_W1d[cc*64 + oo] = dupf(W1[t]*(g1[oo]*rsqrtf(v1[oo]+BN_EPS)));
        g_W2d[cc*64 + oo] = dupf(W2[t]*(g2[oo]*rsqrtf(v2[oo]+BN_EPS)));
    }
}

// ---------------- per-point projections ----------------
__global__ void prep_kernel(const float* __restrict__ feats,
                            const unsigned char* __restrict__ mask)
{
    const int lp = threadIdx.x >> 6;
    const int o  = threadIdx.x & 63;
    const int pt = blockIdx.x*4 + lp;
    __shared__ float sx[4][CF];
    if (o < CF) sx[lp][o] = feats[pt*(2+CF) + 2 + o];
    __syncthreads();
    float a = 0.f, yb = 0.f, sc = 0.f;
#pragma unroll
    for (int c = 0; c < CF; c++){
        float x = sx[lp][c];
        a  = fmaf(x, g_W0at[c*64 + o], a);
        yb = fmaf(x, g_W0bt[c*64 + o], yb);
        sc = fmaf(x, g_Wst [c*64 + o], sc);
    }
    g_C[pt*64 + o] = a + g_t0[o];
    g_Y[pt*64 + o] = yb;
    float scv = sc + g_ts[o];
    if (mask[pt]) scv = 0.f;
    g_SC[pt*64 + o] = scv;
}

// ---------------- KNN: warp-per-point, branch-free bitonic ----------------
__global__ void __launch_bounds__(256)
knn_kernel(const float* __restrict__ feats,
           const unsigned char* __restrict__ mask)
{
    const int n    = blockIdx.x >> 7;
    const int bloc = blockIdx.x & 127;
    const int warp = threadIdx.x >> 5;
    const int lane = threadIdx.x & 31;
    const int p    = bloc*8 + warp;

    __shared__ float px[NP], py[NP], rr[NP];
    __shared__ u32 heads[8][512];
    __shared__ int scnt;

    if (threadIdx.x == 0) scnt = 0;
    int mcnt = 0;
    for (int i = threadIdx.x; i < NP; i += 256){
        float x = feats[(n*NP + i)*(2+CF) + 0];
        float y = feats[(n*NP + i)*(2+CF) + 1];
        px[i] = x; py[i] = y; rr[i] = x*x + y*y;
        if (bloc == 0 && mask[n*NP + i]) mcnt++;
    }
    __syncthreads();
    if (bloc == 0 && mcnt) atomicAdd(&scnt, mcnt);

    const float xp = px[p], yp = py[p], rp = rr[p];
    const float nx = -2.f*xp, ny = -2.f*yp;

    u32 key[32];
#pragma unroll
    for (int i = 0; i < 32; i++){
        int q = i*32 + lane;
        float d = fmaxf(fmaf(nx, px[q], fmaf(ny, py[q], rp + rr[q])), 0.f);
        u32 kb = (__float_as_uint(d) & 0xFFFFFC00u) | (u32)q;
        key[i] = (q == p) ? 0xFFFFFFFFu : kb;
    }
#pragma unroll
    for (int kk = 2; kk <= 32; kk <<= 1){
#pragma unroll
        for (int j = kk >> 1; j > 0; j >>= 1){
#pragma unroll
            for (int i = 0; i < 32; i++){
                int l = i ^ j;
                if (l > i){
                    u32 a = key[i], b = key[l];
                    u32 lo = a < b ? a : b;
                    u32 hi = a < b ? b : a;
                    if ((i & kk) == 0){ key[i] = lo; key[l] = hi; }
                    else              { key[i] = hi; key[l] = lo; }
                }
            }
        }
    }
#pragma unroll
    for (int j = 0; j < 16; j++) heads[warp][j*32 + lane] = key[j];

    int ptr = 0;
    u32 sel = 0;
#pragma unroll 1
    for (int r = 0; r < KK; r++){
        u32 h = (ptr < 16) ? heads[warp][ptr*32 + lane] : 0xFFFFFFFFu;
        u32 w = h;
#pragma unroll
        for (int d = 16; d; d >>= 1){
            u32 o = __shfl_xor_sync(0xFFFFFFFFu, w, d);
            w = (o < w) ? o : w;
        }
        if (h == w) ptr++;
        if (lane == r) sel = w;
    }
    if (lane < KK) g_idx[(n*NP + p)*KK + lane] = (int)(sel & 1023u);

    if (bloc == 0){
        __syncthreads();
        if (threadIdx.x == 0) g_valid[n] = NP - scnt;
    }
}

// ---------------- edge kernel v7: M-paired FMA2, duplicated weights ----------------
// 128 threads, 8 points (128 edge rows x 64 ch). Thread tile 8M x 8N, M split
// into two 4-row groups (m0a, m0a+32) so each act LDS.128 stays in one 128B
// line. Act rows pair naturally into the FMA2 'a' operand (no PACK in loop);
// weights/biases pre-duplicated in GMEM feed 'b' and acc-init directly.
__global__ void __launch_bounds__(128, 4)
edge_kernel(float* __restrict__ out)
{
    __shared__ float act[64*128];     // [c][m], reused between layers
    __shared__ float part[32*64];     // [row-group][o]
    __shared__ float validf[128];
    __shared__ float vcnt[8];

    const int tid = threadIdx.x;
    const int pt0 = blockIdx.x * 8;
    const int n   = pt0 >> 10;
    const int valid = g_valid[n];

    // ---- phase 0: layer-0 activations into act[c][m] ----
    {
        const int m  = tid;
        const int pt = pt0 + (m >> 4);
        const int q  = g_idx[pt*KK + (m & 15)];
        validf[m] = (q < valid) ? 1.f : 0.f;
        const float4* Yq = (const float4*)(g_Y + ((size_t)n*NP + q)*64);
        const float4* Cp = (const float4*)(g_C + (size_t)pt*64);
#pragma unroll
        for (int j = 0; j < 16; j++){
            float4 y = Yq[j];
            float4 c = Cp[j];
            int cc = j*4;
            act[(cc+0)*128 + m] = fmaxf(c.x - y.x, 0.f);
            act[(cc+1)*128 + m] = fmaxf(c.y - y.y, 0.f);
            act[(cc+2)*128 + m] = fmaxf(c.z - y.z, 0.f);
            act[(cc+3)*128 + m] = fmaxf(c.w - y.w, 0.f);
        }
    }
    __syncthreads();

    if (tid < 8){
        float s = 0.f;
#pragma unroll
        for (int j = 0; j < 16; j++) s += validf[tid*16 + j];
        vcnt[tid] = s;
    }

    // ---- tiling: warp = 64M x 32N; thread = (4+4)M x 8N ----
    const int lane  = tid & 31;
    const int warp  = tid >> 5;
    const int mwarp = warp & 1;                    // 2 M-halves of 64
    const int nwarp = warp >> 1;                   // 2 N-halves of 32
    const int m0a   = mwarp*64 + (lane >> 2)*4;    // rows m0a..m0a+3
    const int m0b   = m0a + 32;                    // rows m0b..m0b+3
    const int o0    = nwarp*32 + (lane & 3)*8;     // 8 N cols

    // acc[rp*8+o]: rp0=(m0a,m0a+1) rp1=(m0a+2,m0a+3) rp2/rp3 = m0b rows
    u64 acc[32];

    // ===== layer 1 =====
    {
        const ulonglong2* tp = (const ulonglong2*)(g_t1d + o0);
        ulonglong2 t01 = __ldg(tp), t23 = __ldg(tp+1), t45 = __ldg(tp+2), t67 = __ldg(tp+3);
#pragma unroll
        for (int rp = 0; rp < 4; rp++){
            acc[rp*8+0]=t01.x; acc[rp*8+1]=t01.y; acc[rp*8+2]=t23.x; acc[rp*8+3]=t23.y;
            acc[rp*8+4]=t45.x; acc[rp*8+5]=t45.y; acc[rp*8+6]=t67.x; acc[rp*8+7]=t67.y;
        }
        const float* A0 = act + m0a;
        const float* A1 = act + m0b;
        const u64*   W  = g_W1d + o0;
        ulonglong2 pa0 = *(const ulonglong2*)(A0);
        ulonglong2 pa1 = *(const ulonglong2*)(A1);
        ulonglong2 pw0 = __ldg((const ulonglong2*)(W));
        ulonglong2 pw1 = __ldg((const ulonglong2*)(W + 2));
        ulonglong2 pw2 = __ldg((const ulonglong2*)(W + 4));
        ulonglong2 pw3 = __ldg((const ulonglong2*)(W + 6));
#pragma unroll 8
        for (int c = 0; c < 64; c++){
            ulonglong2 a0 = pa0, a1 = pa1;
            ulonglong2 w0 = pw0, w1 = pw1, w2 = pw2, w3 = pw3;
            const int cn = (c + 1) & 63;
            pa0 = *(const ulonglong2*)(A0 + cn*128);
            pa1 = *(const ulonglong2*)(A1 + cn*128);
            pw0 = __ldg((const ulonglong2*)(W + cn*64));
            pw1 = __ldg((const ulonglong2*)(W + cn*64 + 2));
            pw2 = __ldg((const ulonglong2*)(W + cn*64 + 4));
            pw3 = __ldg((const ulonglong2*)(W + cn*64 + 6));
            FMA2(acc[ 0], a0.x, w0.x, acc[ 0]); FMA2(acc[ 1], a0.x, w0.y, acc[ 1]);
            FMA2(acc[ 2], a0.x, w1.x, acc[ 2]); FMA2(acc[ 3], a0.x, w1.y, acc[ 3]);
            FMA2(acc[ 4], a0.x, w2.x, acc[ 4]); FMA2(acc[ 5], a0.x, w2.y, acc[ 5]);
            FMA2(acc[ 6], a0.x, w3.x, acc[ 6]); FMA2(acc[ 7], a0.x, w3.y, acc[ 7]);
            FMA2(acc[ 8], a0.y, w0.x, acc[ 8]); FMA2(acc[ 9], a0.y, w0.y, acc[ 9]);
            FMA2(acc[10], a0.y, w1.x, acc[10]); FMA2(acc[11], a0.y, w1.y, acc[11]);
            FMA2(acc[12], a0.y, w2.x, acc[12]); FMA2(acc[13], a0.y, w2.y, acc[13]);
            FMA2(acc[14], a0.y, w3.x, acc[14]); FMA2(acc[15], a0.y, w3.y, acc[15]);
            FMA2(acc[16], a1.x, w0.x, acc[16]); FMA2(acc[17], a1.x, w0.y, acc[17]);
            FMA2(acc[18], a1.x, w1.x, acc[18]); FMA2(acc[19], a1.x, w1.y, acc[19]);
            FMA2(acc[20], a1.x, w2.x, acc[20]); FMA2(acc[21], a1.x, w2.y, acc[21]);
            FMA2(acc[22], a1.x, w3.x, acc[22]); FMA2(acc[23], a1.x, w3.y, acc[23]);
            FMA2(acc[24], a1.y, w0.x, acc[24]); FMA2(acc[25], a1.y, w0.y, acc[25]);
            FMA2(acc[26], a1.y, w1.x, acc[26]); FMA2(acc[27], a1.y, w1.y, acc[27]);
            FMA2(acc[28], a1.y, w2.x, acc[28]); FMA2(acc[29], a1.y, w2.y, acc[29]);
            FMA2(acc[30], a1.y, w3.x, acc[30]); FMA2(acc[31], a1.y, w3.y, acc[31]);
        }
    }
    __syncthreads();   // all reads of act complete

    // relu + writeback: M-pairs store contiguously as STS.128
#pragma unroll
    for (int o = 0; o < 8; o++){
        float x0,y0, x1,y1, x2,y2, x3,y3;
        UNPACK2(x0, y0, acc[ 0+o]);
        UNPACK2(x1, y1, acc[ 8+o]);
        UNPACK2(x2, y2, acc[16+o]);
        UNPACK2(x3, y3, acc[24+o]);
        u64 q0, q1, q2, q3;
        PACK2D(q0, fmaxf(x0,0.f), fmaxf(y0,0.f));
        PACK2D(q1, fmaxf(x1,0.f), fmaxf(y1,0.f));
        PACK2D(q2, fmaxf(x2,0.f), fmaxf(y2,0.f));
        PACK2D(q3, fmaxf(x3,0.f), fmaxf(y3,0.f));
        *(ulonglong2*)(act + (o0+o)*128 + m0a) = make_ulonglong2(q0, q1);
        *(ulonglong2*)(act + (o0+o)*128 + m0b) = make_ulonglong2(q2, q3);
    }
    __syncthreads();   // layer-1 activations ready

    // ===== layer 2 =====
    {
        const ulonglong2* tp = (const ulonglong2*)(g_t2d + o0);
        ulonglong2 t01 = __ldg(tp), t23 = __ldg(tp+1), t45 = __ldg(tp+2), t67 = __ldg(tp+3);
#pragma unroll
        for (int rp = 0; rp < 4; rp++){
            acc[rp*8+0]=t01.x; acc[rp*8+1]=t01.y; acc[rp*8+2]=t23.x; acc[rp*8+3]=t23.y;
            acc[rp*8+4]=t45.x; acc[rp*8+5]=t45.y; acc[rp*8+6]=t67.x; acc[rp*8+7]=t67.y;
        }
        const float* A0 = act + m0a;
        const float* A1 = act + m0b;
        const u64*   W  = g_W2d + o0;
        ulonglong2 pa0 = *(const ulonglong2*)(A0);
        ulonglong2 pa1 = *(const ulonglong2*)(A1);
        ulonglong2 pw0 = __ldg((const ulonglong2*)(W));
        ulonglong2 pw1 = __ldg((const ulonglong2*)(W + 2));
        ulonglong2 pw2 = __ldg((const ulonglong2*)(W + 4));
        ulonglong2 pw3 = __ldg((const ulonglong2*)(W + 6));
#pragma unroll 8
        for (int c = 0; c < 64; c++){
            ulonglong2 a0 = pa0, a1 = pa1;
            ulonglong2 w0 = pw0, w1 = pw1, w2 = pw2, w3 = pw3;
            const int cn = (c + 1) & 63;
            pa0 = *(const ulonglong2*)(A0 + cn*128);
            pa1 = *(const ulonglong2*)(A1 + cn*128);
            pw0 = __ldg((const ulonglong2*)(W + cn*64));
            pw1 = __ldg((const ulonglong2*)(W + cn*64 + 2));
            pw2 = __ldg((const ulonglong2*)(W + cn*64 + 4));
            pw3 = __ldg((const ulonglong2*)(W + cn*64 + 6));
            FMA2(acc[ 0], a0.x, w0.x, acc[ 0]); FMA2(acc[ 1], a0.x, w0.y, acc[ 1]);
            FMA2(acc[ 2], a0.x, w1.x, acc[ 2]); FMA2(acc[ 3], a0.x, w1.y, acc[ 3]);
            FMA2(acc[ 4], a0.x, w2.x, acc[ 4]); FMA2(acc[ 5], a0.x, w2.y, acc[ 5]);
            FMA2(acc[ 6], a0.x, w3.x, acc[ 6]); FMA2(acc[ 7], a0.x, w3.y, acc[ 7]);
            FMA2(acc[ 8], a0.y, w0.x, acc[ 8]); FMA2(acc[ 9], a0.y, w0.y, acc[ 9]);
            FMA2(acc[10], a0.y, w1.x, acc[10]); FMA2(acc[11], a0.y, w1.y, acc[11]);
            FMA2(acc[12], a0.y, w2.x, acc[12]); FMA2(acc[13], a0.y, w2.y, acc[13]);
            FMA2(acc[14], a0.y, w3.x, acc[14]); FMA2(acc[15], a0.y, w3.y, acc[15]);
            FMA2(acc[16], a1.x, w0.x, acc[16]); FMA2(acc[17], a1.x, w0.y, acc[17]);
            FMA2(acc[18], a1.x, w1.x, acc[18]); FMA2(acc[19], a1.x, w1.y, acc[19]);
            FMA2(acc[20], a1.x, w2.x, acc[20]); FMA2(acc[21], a1.x, w2.y, acc[21]);
            FMA2(acc[22], a1.x, w3.x, acc[22]); FMA2(acc[23], a1.x, w3.y, acc[23]);
            FMA2(acc[24], a1.y, w0.x, acc[24]); FMA2(acc[25], a1.y, w0.y, acc[25]);
            FMA2(acc[26], a1.y, w1.x, acc[26]); FMA2(acc[27], a1.y, w1.y, acc[27]);
            FMA2(acc[28], a1.y, w2.x, acc[28]); FMA2(acc[29], a1.y, w2.y, acc[29]);
            FMA2(acc[30], a1.y, w3.x, acc[30]); FMA2(acc[31], a1.y, w3.y, acc[31]);
        }
    }

    // ===== epilogue: relu + masked per-row-group partials =====
    {
        const float va0 = validf[m0a+0], va1 = validf[m0a+1];
        const float va2 = validf[m0a+2], va3 = validf[m0a+3];
        const float vb0 = validf[m0b+0], vb1 = validf[m0b+1];
        const float vb2 = validf[m0b+2], vb3 = validf[m0b+3];
        const int ga = m0a >> 2, gb = m0b >> 2;
#pragma unroll
        for (int o = 0; o < 8; o++){
            float x0,y0, x1,y1, x2,y2, x3,y3;
            UNPACK2(x0, y0, acc[ 0+o]);
            UNPACK2(x1, y1, acc[ 8+o]);
            UNPACK2(x2, y2, acc[16+o]);
            UNPACK2(x3, y3, acc[24+o]);
            part[ga*64 + o0+o] = fmaxf(x0,0.f)*va0 + fmaxf(y0,0.f)*va1
                               + fmaxf(x1,0.f)*va2 + fmaxf(y1,0.f)*va3;
            part[gb*64 + o0+o] = fmaxf(x2,0.f)*vb0 + fmaxf(y2,0.f)*vb1
                               + fmaxf(x3,0.f)*vb2 + fmaxf(y3,0.f)*vb3;
        }
    }
    __syncthreads();

    // ===== final: deterministic 4-group sum + mean + shortcut + relu =====
#pragma unroll
    for (int s = 0; s < 4; s++){
        const int idx = tid + s*128;        // 512 outputs: 8 points x 64 ch
        const int o   = idx >> 3;
        const int pl  = idx & 7;
        const int pt  = pt0 + pl;
        const int p   = pt & (NP-1);
        float sum = part[(pl*4+0)*64 + o] + part[(pl*4+1)*64 + o]
                  + part[(pl*4+2)*64 + o] + part[(pl*4+3)*64 + o];
        float denom = fmaxf(vcnt[pl], 1e-8f);
        float res = fmaxf(sum/denom + g_SC[(size_t)pt*64 + o], 0.f);
        out[((size_t)n*64 + o)*NP + p] = res;
    }
}

// ---------------- launch ----------------
extern "C" void kernel_launch(void* const* d_in, const int* in_sizes, int n_in,
                              void* d_out, int out_size)
{
    const float* feats = (const float*)d_in[0];
    const unsigned char* mask = (const unsigned char*)d_in[1];
    const float* W0 = (const float*)d_in[2];
    const float* W1 = (const float*)d_in[3];
    const float* W2 = (const float*)d_in[4];
    const float* Ws = (const float*)d_in[5];

    fold_kernel<<<16, 256>>>(W0, W1, W2, Ws,
        (const float*)d_in[6],  (const float*)d_in[7],  (const float*)d_in[8],  (const float*)d_in[9],
        (const float*)d_in[10], (const float*)d_in[11], (const float*)d_in[12], (const float*)d_in[13],
        (const float*)d_in[14], (const float*)d_in[15], (const float*)d_in[16], (const float*)d_in[17],
        (const float*)d_in[18], (const float*)d_in[19], (const float*)d_in[20], (const float*)d_in[21]);

    prep_kernel<<<NB*NP/4, 256>>>(feats, mask);
    knn_kernel<<<NB*128, 256>>>(feats, mask);
    edge_kernel<<<NB*NP/8, 128>>>((float*)d_out);
}

// round 11
// speedup vs baseline: 1.4335x; 1.4335x over previous
#include <cuda_runtime.h>

#define NB 64
#define NP 1024
#define CF 16
#define KK 16
#define BN_EPS 1e-5f

typedef unsigned long long u64;

#define FMA2(d, a, b, c) \
    asm("fma.rn.f32x2 %0, %1, %2, %3;" : "=l"(d) : "l"(a), "l"(b), "l"(c))
#define PACK2(d, x) \
    asm("mov.b64 %0, {%1, %1};" : "=l"(d) : "f"(x))
#define UNPACK2(lo, hi, v) \
    asm("mov.b64 {%0, %1}, %2;" : "=f"(lo), "=f"(hi) : "l"(v))

// ---------------- static scratch (no allocations allowed) ----------------
__device__ float g_C [NB*NP*64];
__device__ float g_Y [NB*NP*64];
__device__ float g_SC[NB*NP*64];
__device__ int   g_idx[NB*NP*KK];
__device__ int   g_valid[NB];
__device__ float g_W1t[64*64];     // W1 (BN-scaled), TRANSPOSED [c][o]
__device__ float g_W2t[64*64];
__device__ float g_W0at[CF*64], g_W0bt[CF*64], g_Wst[CF*64];
__device__ float g_t0[64], g_t1[64], g_t2[64], g_ts[64];

// ---------------- fold BN into weights / biases ----------------
__global__ void fold_kernel(const float* __restrict__ W0, const float* __restrict__ W1,
    const float* __restrict__ W2, const float* __restrict__ Ws,
    const float* g0,const float* b0,const float* m0,const float* v0,
    const float* g1,const float* b1,const float* m1,const float* v1,
    const float* g2,const float* b2,const float* m2,const float* v2,
    const float* gs,const float* bs,const float* ms,const float* vs)
{
    int t = blockIdx.x*blockDim.x + threadIdx.x;
    if (t < 64){
        float s0 = g0[t]*rsqrtf(v0[t]+BN_EPS); g_t0[t]=b0[t]-m0[t]*s0;
        float s1 = g1[t]*rsqrtf(v1[t]+BN_EPS); g_t1[t]=b1[t]-m1[t]*s1;
        float s2 = g2[t]*rsqrtf(v2[t]+BN_EPS); g_t2[t]=b2[t]-m2[t]*s2;
        float ss = gs[t]*rsqrtf(vs[t]+BN_EPS); g_ts[t]=bs[t]-ms[t]*ss;
    }
    if (t < 1024){
        int o = t >> 4, c = t & 15;
        float s0 = g0[o]*rsqrtf(v0[o]+BN_EPS);
        float ss = gs[o]*rsqrtf(vs[o]+BN_EPS);
        float wa = W0[o*32 + c], wb = W0[o*32 + 16 + c];
        g_W0at[c*64 + o] = (wa + wb)*s0;
        g_W0bt[c*64 + o] = wb*s0;
        g_Wst [c*64 + o] = Ws[o*16 + c]*ss;
    }
    if (t < 4096){
        int oo = t >> 6, cc = t & 63;
        g_W1t[cc*64 + oo] = W1[t]*(g1[oo]*rsqrtf(v1[oo]+BN_EPS));
        g_W2t[cc*64 + oo] = W2[t]*(g2[oo]*rsqrtf(v2[oo]+BN_EPS));
    }
}

// ---------------- per-point projections ----------------
__global__ void prep_kernel(const float* __restrict__ feats,
                            const unsigned char* __restrict__ mask)
{
    const int lp = threadIdx.x >> 6;
    const int o  = threadIdx.x & 63;
    const int pt = blockIdx.x*4 + lp;
    __shared__ float sx[4][CF];
    if (o < CF) sx[lp][o] = feats[pt*(2+CF) + 2 + o];
    __syncthreads();
    float a = 0.f, yb = 0.f, sc = 0.f;
#pragma unroll
    for (int c = 0; c < CF; c++){
        float x = sx[lp][c];
        a  = fmaf(x, g_W0at[c*64 + o], a);
        yb = fmaf(x, g_W0bt[c*64 + o], yb);
        sc = fmaf(x, g_Wst [c*64 + o], sc);
    }
    g_C[pt*64 + o] = a + g_t0[o];
    g_Y[pt*64 + o] = yb;
    float scv = sc + g_ts[o];
    if (mask[pt]) scv = 0.f;
    g_SC[pt*64 + o] = scv;
}

// ---------------- KNN: warp-per-point, branch-free bitonic ----------------
__global__ void __launch_bounds__(256)
knn_kernel(const float* __restrict__ feats,
           const unsigned char* __restrict__ mask)
{
    const int n    = blockIdx.x >> 7;
    const int bloc = blockIdx.x & 127;
    const int warp = threadIdx.x >> 5;
    const int lane = threadIdx.x & 31;
    const int p    = bloc*8 + warp;

    __shared__ float px[NP], py[NP], rr[NP];
    __shared__ unsigned int heads[8][512];
    __shared__ int scnt;

    if (threadIdx.x == 0) scnt = 0;
    int mcnt = 0;
    for (int i = threadIdx.x; i < NP; i += 256){
        float x = feats[(n*NP + i)*(2+CF) + 0];
        float y = feats[(n*NP + i)*(2+CF) + 1];
        px[i] = x; py[i] = y; rr[i] = x*x + y*y;
        if (bloc == 0 && mask[n*NP + i]) mcnt++;
    }
    __syncthreads();
    if (bloc == 0 && mcnt) atomicAdd(&scnt, mcnt);

    const float xp = px[p], yp = py[p], rp = rr[p];
    const float nx = -2.f*xp, ny = -2.f*yp;

    unsigned int key[32];
#pragma unroll
    for (int i = 0; i < 32; i++){
        int q = i*32 + lane;
        float d = fmaxf(fmaf(nx, px[q], fmaf(ny, py[q], rp + rr[q])), 0.f);
        unsigned int kb = (__float_as_uint(d) & 0xFFFFFC00u) | (unsigned int)q;
        key[i] = (q == p) ? 0xFFFFFFFFu : kb;
    }
#pragma unroll
    for (int kk = 2; kk <= 32; kk <<= 1){
#pragma unroll
        for (int j = kk >> 1; j > 0; j >>= 1){
#pragma unroll
            for (int i = 0; i < 32; i++){
                int l = i ^ j;
                if (l > i){
                    unsigned int a = key[i], b = key[l];
                    unsigned int lo = a < b ? a : b;
                    unsigned int hi = a < b ? b : a;
                    if ((i & kk) == 0){ key[i] = lo; key[l] = hi; }
                    else              { key[i] = hi; key[l] = lo; }
                }
            }
        }
    }
#pragma unroll
    for (int j = 0; j < 16; j++) heads[warp][j*32 + lane] = key[j];

    int ptr = 0;
    unsigned int sel = 0;
#pragma unroll 1
    for (int r = 0; r < KK; r++){
        unsigned int h = (ptr < 16) ? heads[warp][ptr*32 + lane] : 0xFFFFFFFFu;
        unsigned int w = h;
#pragma unroll
        for (int d = 16; d; d >>= 1){
            unsigned int o = __shfl_xor_sync(0xFFFFFFFFu, w, d);
            w = (o < w) ? o : w;
        }
        if (h == w) ptr++;
        if (lane == r) sel = w;
    }
    if (lane < KK) g_idx[(n*NP + p)*KK + lane] = (int)(sel & 1023u);

    if (bloc == 0){
        __syncthreads();
        if (threadIdx.x == 0) g_valid[n] = NP - scnt;
    }
}

// ---------------- edge kernel v8: R6 tiling + SMEM-staged weights ----------------
// Identical warp-local 32Mx32N tiling to R6 (best so far), but the inner-loop
// weight reads come from SMEM (staged once per layer, 16KB) instead of 2048
// LDG instructions/block -- removing the LSU dispatch floor (LDG->LDG = 4cyc)
// that stacked with the FMA2 floor. Inner loop: 3 LDS.128 + 4 PACK2 + 16 FMA2.
// 'part' overlaps the dead act region after layer 2 (one extra barrier).
#define SM_ACT    0                    // 64*128 floats = 32768 B (part overlaps)
#define SM_W      32768                // 64*64 floats  = 16384 B (one layer at a time)
#define SM_VALIDF 49152                // 128 floats
#define SM_VCNT   49664                // 8 floats
#define SM_TOTAL  49696

__global__ void __launch_bounds__(256)
edge_kernel(float* __restrict__ out)
{
    extern __shared__ char smraw[];
    float* act    = (float*)(smraw + SM_ACT);
    float* wsm    = (float*)(smraw + SM_W);
    float* part   = (float*)(smraw + SM_ACT);     // overlaps act (used after L2)
    float* validf = (float*)(smraw + SM_VALIDF);
    float* vcnt   = (float*)(smraw + SM_VCNT);

    const int tid = threadIdx.x;
    const int pt0 = blockIdx.x * 8;
    const int n   = pt0 >> 10;

    const int valid = g_valid[n];

    // ---- phase 0: layer-0 activations into act[c][m]; stage W1 into SMEM ----
    {
        const int m  = tid >> 1;
        const int h  = tid & 1;
        const int pt = pt0 + (m >> 4);
        const int q  = g_idx[pt*KK + (m & 15)];
        if (h == 0) validf[m] = (q < valid) ? 1.f : 0.f;
        const float4* Yq = (const float4*)(g_Y + ((size_t)n*NP + q)*64) + h*8;
        const float4* Cp = (const float4*)(g_C + (size_t)pt*64) + h*8;
#pragma unroll
        for (int j = 0; j < 8; j++){
            float4 y = Yq[j];
            float4 c = Cp[j];
            int cc = h*32 + j*4;
            act[(cc+0)*128 + m] = fmaxf(c.x - y.x, 0.f);
            act[(cc+1)*128 + m] = fmaxf(c.y - y.y, 0.f);
            act[(cc+2)*128 + m] = fmaxf(c.z - y.z, 0.f);
            act[(cc+3)*128 + m] = fmaxf(c.w - y.w, 0.f);
        }
        const float4* src = (const float4*)g_W1t;
        float4* dst = (float4*)wsm;
#pragma unroll
        for (int i = 0; i < 4; i++) dst[tid + i*256] = __ldg(src + tid + i*256);
    }
    __syncthreads();

    if (tid < 8){
        float s = 0.f;
#pragma unroll
        for (int j = 0; j < 16; j++) s += validf[tid*16 + j];
        vcnt[tid] = s;
    }

    // ---- warp-local tiling (identical to R6) ----
    const int lane  = tid & 31;
    const int warp  = tid >> 5;
    const int mwarp = warp & 3;          // 4 M-groups of 32
    const int nwarp = warp >> 2;         // 2 N-groups of 32
    const int m0    = mwarp*32 + (lane >> 2)*4;   // 4 M rows
    const int o0    = nwarp*32 + (lane & 3)*8;    // 8 N cols
    const int mtg   = m0 >> 2;           // global M-tile index 0..31

    u64 acc[16];   // acc[mi*4+oj] = packed (o0+2oj, o0+2oj+1) for row m0+mi

    // ===== layer 1 =====
    {
        const u64* tp = (const u64*)(g_t1 + o0);
        u64 t0p = tp[0], t1p = tp[1], t2p = tp[2], t3p = tp[3];
#pragma unroll
        for (int mi = 0; mi < 4; mi++){
            acc[mi*4+0]=t0p; acc[mi*4+1]=t1p; acc[mi*4+2]=t2p; acc[mi*4+3]=t3p;
        }
        const float* W = wsm + o0;
#pragma unroll 8
        for (int c = 0; c < 64; c++){
            float4 a = *(const float4*)(act + c*128 + m0);
            u64 ax, ay, az, aw;
            PACK2(ax, a.x); PACK2(ay, a.y); PACK2(az, a.z); PACK2(aw, a.w);
            ulonglong2 b01 = *(const ulonglong2*)(W + c*64);
            ulonglong2 b23 = *(const ulonglong2*)(W + c*64 + 4);
            FMA2(acc[ 0], ax, b01.x, acc[ 0]); FMA2(acc[ 1], ax, b01.y, acc[ 1]);
            FMA2(acc[ 2], ax, b23.x, acc[ 2]); FMA2(acc[ 3], ax, b23.y, acc[ 3]);
            FMA2(acc[ 4], ay, b01.x, acc[ 4]); FMA2(acc[ 5], ay, b01.y, acc[ 5]);
            FMA2(acc[ 6], ay, b23.x, acc[ 6]); FMA2(acc[ 7], ay, b23.y, acc[ 7]);
            FMA2(acc[ 8], az, b01.x, acc[ 8]); FMA2(acc[ 9], az, b01.y, acc[ 9]);
            FMA2(acc[10], az, b23.x, acc[10]); FMA2(acc[11], az, b23.y, acc[11]);
            FMA2(acc[12], aw, b01.x, acc[12]); FMA2(acc[13], aw, b01.y, acc[13]);
            FMA2(acc[14], aw, b23.x, acc[14]); FMA2(acc[15], aw, b23.y, acc[15]);
        }
    }
    __syncthreads();   // all reads of act + wsm(W1) complete

    // relu + transposed writeback via STS.128; stage W2 into SMEM
#pragma unroll
    for (int oj = 0; oj < 4; oj++){
        float lo0,hi0, lo1,hi1, lo2,hi2, lo3,hi3;
        UNPACK2(lo0, hi0, acc[ 0+oj]);
        UNPACK2(lo1, hi1, acc[ 4+oj]);
        UNPACK2(lo2, hi2, acc[ 8+oj]);
        UNPACK2(lo3, hi3, acc[12+oj]);
        float4 vlo = { fmaxf(lo0,0.f), fmaxf(lo1,0.f), fmaxf(lo2,0.f), fmaxf(lo3,0.f) };
        float4 vhi = { fmaxf(hi0,0.f), fmaxf(hi1,0.f), fmaxf(hi2,0.f), fmaxf(hi3,0.f) };
        *(float4*)(act + (o0 + 2*oj    )*128 + m0) = vlo;
        *(float4*)(act + (o0 + 2*oj + 1)*128 + m0) = vhi;
    }
    {
        const float4* src = (const float4*)g_W2t;
        float4* dst = (float4*)wsm;
#pragma unroll
        for (int i = 0; i < 4; i++) dst[tid + i*256] = __ldg(src + tid + i*256);
    }
    __syncthreads();   // layer-1 activations + W2 ready

    // ===== layer 2 =====
    {
        const u64* tp = (const u64*)(g_t2 + o0);
        u64 t0p = tp[0], t1p = tp[1], t2p = tp[2], t3p = tp[3];
#pragma unroll
        for (int mi = 0; mi < 4; mi++){
            acc[mi*4+0]=t0p; acc[mi*4+1]=t1p; acc[mi*4+2]=t2p; acc[mi*4+3]=t3p;
        }
        const float* W = wsm + o0;
#pragma unroll 8
        for (int c = 0; c < 64; c++){
            float4 a = *(const float4*)(act + c*128 + m0);
            u64 ax, ay, az, aw;
            PACK2(ax, a.x); PACK2(ay, a.y); PACK2(az, a.z); PACK2(aw, a.w);
            ulonglong2 b01 = *(const ulonglong2*)(W + c*64);
            ulonglong2 b23 = *(const ulonglong2*)(W + c*64 + 4);
            FMA2(acc[ 0], ax, b01.x, acc[ 0]); FMA2(acc[ 1], ax, b01.y, acc[ 1]);
            FMA2(acc[ 2], ax, b23.x, acc[ 2]); FMA2(acc[ 3], ax, b23.y, acc[ 3]);
            FMA2(acc[ 4], ay, b01.x, acc[ 4]); FMA2(acc[ 5], ay, b01.y, acc[ 5]);
            FMA2(acc[ 6], ay, b23.x, acc[ 6]); FMA2(acc[ 7], ay, b23.y, acc[ 7]);
            FMA2(acc[ 8], az, b01.x, acc[ 8]); FMA2(acc[ 9], az, b01.y, acc[ 9]);
            FMA2(acc[10], az, b23.x, acc[10]); FMA2(acc[11], az, b23.y, acc[11]);
            FMA2(acc[12], aw, b01.x, acc[12]); FMA2(acc[13], aw, b01.y, acc[13]);
            FMA2(acc[14], aw, b23.x, acc[14]); FMA2(acc[15], aw, b23.y, acc[15]);
        }
    }
    __syncthreads();   // all reads of act complete (part overlaps act)

    // ===== epilogue: relu + masked per-point partials (into act region) =====
    {
        const float vf0 = validf[m0+0], vf1 = validf[m0+1];
        const float vf2 = validf[m0+2], vf3 = validf[m0+3];
#pragma unroll
        for (int oj = 0; oj < 4; oj++){
            float lo0,hi0, lo1,hi1, lo2,hi2, lo3,hi3;
            UNPACK2(lo0, hi0, acc[ 0+oj]);
            UNPACK2(lo1, hi1, acc[ 4+oj]);
            UNPACK2(lo2, hi2, acc[ 8+oj]);
            UNPACK2(lo3, hi3, acc[12+oj]);
            float slo = fmaxf(lo0,0.f)*vf0 + fmaxf(lo1,0.f)*vf1
                      + fmaxf(lo2,0.f)*vf2 + fmaxf(lo3,0.f)*vf3;
            float shi = fmaxf(hi0,0.f)*vf0 + fmaxf(hi1,0.f)*vf1
                      + fmaxf(hi2,0.f)*vf2 + fmaxf(hi3,0.f)*vf3;
            part[mtg*64 + o0 + 2*oj    ] = slo;
            part[mtg*64 + o0 + 2*oj + 1] = shi;
        }
    }
    __syncthreads();

    // ===== final: deterministic 4-way sum + mean + shortcut + relu =====
#pragma unroll
    for (int s = 0; s < 2; s++){
        const int idx = tid + s*256;
        const int o   = idx >> 3;
        const int pl  = idx & 7;
        const int pt  = pt0 + pl;
        const int p   = pt & (NP-1);
        float sum = part[(pl*4+0)*64 + o] + part[(pl*4+1)*64 + o]
                  + part[(pl*4+2)*64 + o] + part[(pl*4+3)*64 + o];
        float denom = fmaxf(vcnt[pl], 1e-8f);
        float res = fmaxf(sum/denom + g_SC[(size_t)pt*64 + o], 0.f);
        out[((size_t)n*64 + o)*NP + p] = res;
    }
}

// ---------------- launch ----------------
extern "C" void kernel_launch(void* const* d_in, const int* in_sizes, int n_in,
                              void* d_out, int out_size)
{
    const float* feats = (const float*)d_in[0];
    const unsigned char* mask = (const unsigned char*)d_in[1];
    const float* W0 = (const float*)d_in[2];
    const float* W1 = (const float*)d_in[3];
    const float* W2 = (const float*)d_in[4];
    const float* Ws = (const float*)d_in[5];

    cudaFuncSetAttribute(edge_kernel, cudaFuncAttributeMaxDynamicSharedMemorySize, SM_TOTAL);

    fold_kernel<<<16, 256>>>(W0, W1, W2, Ws,
        (const float*)d_in[6],  (const float*)d_in[7],  (const float*)d_in[8],  (const float*)d_in[9],
        (const float*)d_in[10], (const float*)d_in[11], (const float*)d_in[12], (const float*)d_in[13],
        (const float*)d_in[14], (const float*)d_in[15], (const float*)d_in[16], (const float*)d_in[17],
        (const float*)d_in[18], (const float*)d_in[19], (const float*)d_in[20], (const float*)d_in[21]);

    prep_kernel<<<NB*NP/4, 256>>>(feats, mask);
    knn_kernel<<<NB*128, 256>>>(feats, mask);
    edge_kernel<<<NB*NP/8, 256, SM_TOTAL>>>((float*)d_out);
}

// round 12
// speedup vs baseline: 1.4975x; 1.0446x over previous
#include <cuda_runtime.h>

#define NB 64
#define NP 1024
#define CF 16
#define KK 16
#define BN_EPS 1e-5f

typedef unsigned long long u64;

#define FMA2(d, a, b, c) \
    asm("fma.rn.f32x2 %0, %1, %2, %3;" : "=l"(d) : "l"(a), "l"(b), "l"(c))
#define PACK2(d, x) \
    asm("mov.b64 %0, {%1, %1};" : "=l"(d) : "f"(x))
#define UNPACK2(lo, hi, v) \
    asm("mov.b64 {%0, %1}, %2;" : "=f"(lo), "=f"(hi) : "l"(v))

// ---------------- static scratch (no allocations allowed) ----------------
__device__ float g_C [NB*NP*64];
__device__ float g_Y [NB*NP*64];
__device__ float g_SC[NB*NP*64];
__device__ int   g_idx[NB*NP*KK];
__device__ int   g_valid[NB];
__device__ float g_W1t[64*64];     // W1 (BN-scaled), TRANSPOSED [c][o]
__device__ float g_W2t[64*64];
__device__ float g_W0at[CF*64], g_W0bt[CF*64], g_Wst[CF*64];
__device__ float g_t0[64], g_t1[64], g_t2[64], g_ts[64];

// ---------------- fold BN into weights / biases ----------------
__global__ void fold_kernel(const float* __restrict__ W0, const float* __restrict__ W1,
    const float* __restrict__ W2, const float* __restrict__ Ws,
    const float* g0,const float* b0,const float* m0,const float* v0,
    const float* g1,const float* b1,const float* m1,const float* v1,
    const float* g2,const float* b2,const float* m2,const float* v2,
    const float* gs,const float* bs,const float* ms,const float* vs)
{
    int t = blockIdx.x*blockDim.x + threadIdx.x;
    if (t < 64){
        float s0 = g0[t]*rsqrtf(v0[t]+BN_EPS); g_t0[t]=b0[t]-m0[t]*s0;
        float s1 = g1[t]*rsqrtf(v1[t]+BN_EPS); g_t1[t]=b1[t]-m1[t]*s1;
        float s2 = g2[t]*rsqrtf(v2[t]+BN_EPS); g_t2[t]=b2[t]-m2[t]*s2;
        float ss = gs[t]*rsqrtf(vs[t]+BN_EPS); g_ts[t]=bs[t]-ms[t]*ss;
    }
    if (t < 1024){
        int o = t >> 4, c = t & 15;
        float s0 = g0[o]*rsqrtf(v0[o]+BN_EPS);
        float ss = gs[o]*rsqrtf(vs[o]+BN_EPS);
        float wa = W0[o*32 + c], wb = W0[o*32 + 16 + c];
        g_W0at[c*64 + o] = (wa + wb)*s0;
        g_W0bt[c*64 + o] = wb*s0;
        g_Wst [c*64 + o] = Ws[o*16 + c]*ss;
    }
    if (t < 4096){
        int oo = t >> 6, cc = t & 63;
        g_W1t[cc*64 + oo] = W1[t]*(g1[oo]*rsqrtf(v1[oo]+BN_EPS));
        g_W2t[cc*64 + oo] = W2[t]*(g2[oo]*rsqrtf(v2[oo]+BN_EPS));
    }
}

// ---------------- per-point projections ----------------
__global__ void prep_kernel(const float* __restrict__ feats,
                            const unsigned char* __restrict__ mask)
{
    const int lp = threadIdx.x >> 6;
    const int o  = threadIdx.x & 63;
    const int pt = blockIdx.x*4 + lp;
    __shared__ float sx[4][CF];
    if (o < CF) sx[lp][o] = feats[pt*(2+CF) + 2 + o];
    __syncthreads();
    float a = 0.f, yb = 0.f, sc = 0.f;
#pragma unroll
    for (int c = 0; c < CF; c++){
        float x = sx[lp][c];
        a  = fmaf(x, g_W0at[c*64 + o], a);
        yb = fmaf(x, g_W0bt[c*64 + o], yb);
        sc = fmaf(x, g_Wst [c*64 + o], sc);
    }
    g_C[pt*64 + o] = a + g_t0[o];
    g_Y[pt*64 + o] = yb;
    float scv = sc + g_ts[o];
    if (mask[pt]) scv = 0.f;
    g_SC[pt*64 + o] = scv;
}

// ---------------- KNN: warp-per-point, branch-free bitonic ----------------
__global__ void __launch_bounds__(256)
knn_kernel(const float* __restrict__ feats,
           const unsigned char* __restrict__ mask)
{
    const int n    = blockIdx.x >> 7;
    const int bloc = blockIdx.x & 127;
    const int warp = threadIdx.x >> 5;
    const int lane = threadIdx.x & 31;
    const int p    = bloc*8 + warp;

    __shared__ float px[NP], py[NP], rr[NP];
    __shared__ unsigned int heads[8][512];
    __shared__ int scnt;

    if (threadIdx.x == 0) scnt = 0;
    int mcnt = 0;
    for (int i = threadIdx.x; i < NP; i += 256){
        float x = feats[(n*NP + i)*(2+CF) + 0];
        float y = feats[(n*NP + i)*(2+CF) + 1];
        px[i] = x; py[i] = y; rr[i] = x*x + y*y;
        if (bloc == 0 && mask[n*NP + i]) mcnt++;
    }
    __syncthreads();
    if (bloc == 0 && mcnt) atomicAdd(&scnt, mcnt);

    const float xp = px[p], yp = py[p], rp = rr[p];
    const float nx = -2.f*xp, ny = -2.f*yp;

    unsigned int key[32];
#pragma unroll
    for (int i = 0; i < 32; i++){
        int q = i*32 + lane;
        float d = fmaxf(fmaf(nx, px[q], fmaf(ny, py[q], rp + rr[q])), 0.f);
        unsigned int kb = (__float_as_uint(d) & 0xFFFFFC00u) | (unsigned int)q;
        key[i] = (q == p) ? 0xFFFFFFFFu : kb;
    }
#pragma unroll
    for (int kk = 2; kk <= 32; kk <<= 1){
#pragma unroll
        for (int j = kk >> 1; j > 0; j >>= 1){
#pragma unroll
            for (int i = 0; i < 32; i++){
                int l = i ^ j;
                if (l > i){
                    unsigned int a = key[i], b = key[l];
                    unsigned int lo = a < b ? a : b;
                    unsigned int hi = a < b ? b : a;
                    if ((i & kk) == 0){ key[i] = lo; key[l] = hi; }
                    else              { key[i] = hi; key[l] = lo; }
                }
            }
        }
    }
#pragma unroll
    for (int j = 0; j < 16; j++) heads[warp][j*32 + lane] = key[j];

    int ptr = 0;
    unsigned int sel = 0;
#pragma unroll 1
    for (int r = 0; r < KK; r++){
        unsigned int h = (ptr < 16) ? heads[warp][ptr*32 + lane] : 0xFFFFFFFFu;
        unsigned int w = h;
#pragma unroll
        for (int d = 16; d; d >>= 1){
            unsigned int o = __shfl_xor_sync(0xFFFFFFFFu, w, d);
            w = (o < w) ? o : w;
        }
        if (h == w) ptr++;
        if (lane == r) sel = w;
    }
    if (lane < KK) g_idx[(n*NP + p)*KK + lane] = (int)(sel & 1023u);

    if (bloc == 0){
        __syncthreads();
        if (threadIdx.x == 0) g_valid[n] = NP - scnt;
    }
}

// ---------------- edge kernel v9: 8Mx8N thread tile, SMEM weights ----------------
// 128 threads, 8 points (M=128 x N=64). Thread tile 8M x 8N -> per warp-kstep
// RF traffic is 4 LDS.128 (16 wf) feeding 32 FMA2: LSU budget (8192 wf/block)
// now EQUALS the FMA2 floor (8192 cyc/block), vs R11's 12288 LSU-bound.
#define SM_ACT    0                    // 64*128 floats = 32768 B (part overlaps)
#define SM_W      32768                // 64*64 floats = 16384 B (one layer at a time)
#define SM_VALIDF 49152                // 128 floats
#define SM_VCNT   49664                // 8 floats
#define SM_TOTAL  49696

__global__ void __launch_bounds__(128)
edge_kernel(float* __restrict__ out)
{
    extern __shared__ char smraw[];
    float* act    = (float*)(smraw + SM_ACT);
    float* wsm    = (float*)(smraw + SM_W);
    float* part   = (float*)(smraw + SM_ACT);     // overlaps act (used after L2)
    float* validf = (float*)(smraw + SM_VALIDF);
    float* vcnt   = (float*)(smraw + SM_VCNT);

    const int tid = threadIdx.x;
    const int pt0 = blockIdx.x * 8;
    const int n   = pt0 >> 10;

    const int valid = g_valid[n];

    // ---- phase 0: layer-0 activations into act[c][m]; stage W1 ----
    {
        const int m  = tid;
        const int pt = pt0 + (m >> 4);
        const int q  = g_idx[pt*KK + (m & 15)];
        validf[m] = (q < valid) ? 1.f : 0.f;
        const float4* Yq = (const float4*)(g_Y + ((size_t)n*NP + q)*64);
        const float4* Cp = (const float4*)(g_C + (size_t)pt*64);
#pragma unroll
        for (int j = 0; j < 16; j++){
            float4 y = Yq[j];
            float4 c = Cp[j];
            int cc = j*4;
            act[(cc+0)*128 + m] = fmaxf(c.x - y.x, 0.f);
            act[(cc+1)*128 + m] = fmaxf(c.y - y.y, 0.f);
            act[(cc+2)*128 + m] = fmaxf(c.z - y.z, 0.f);
            act[(cc+3)*128 + m] = fmaxf(c.w - y.w, 0.f);
        }
        const float4* src = (const float4*)g_W1t;
        float4* dst = (float4*)wsm;
#pragma unroll
        for (int i = 0; i < 8; i++) dst[tid + i*128] = __ldg(src + tid + i*128);
    }
    __syncthreads();

    if (tid < 8){
        float s = 0.f;
#pragma unroll
        for (int j = 0; j < 16; j++) s += validf[tid*16 + j];
        vcnt[tid] = s;
    }

    // ---- tiling: 16 M-tiles x 8 N-tiles; thread = 8M x 8N ----
    const int mt = tid & 15;
    const int nt = tid >> 4;
    const int m0 = mt * 8;
    const int o0 = nt * 8;

    // acc[mi*4 + oj] = packed outputs (o0+2oj, o0+2oj+1) for M-row m0+mi
    u64 acc[32];

    // ===== layer 1 =====
    {
        const u64* tp = (const u64*)(g_t1 + o0);
        u64 t0p = tp[0], t1p = tp[1], t2p = tp[2], t3p = tp[3];
#pragma unroll
        for (int mi = 0; mi < 8; mi++){
            acc[mi*4+0]=t0p; acc[mi*4+1]=t1p; acc[mi*4+2]=t2p; acc[mi*4+3]=t3p;
        }
        const float* W = wsm + o0;
#pragma unroll 4
        for (int c = 0; c < 64; c++){
            float4 a0 = *(const float4*)(act + c*128 + m0);
            float4 a1 = *(const float4*)(act + c*128 + m0 + 4);
            ulonglong2 b01 = *(const ulonglong2*)(W + c*64);
            ulonglong2 b23 = *(const ulonglong2*)(W + c*64 + 4);
            u64 d0,d1,d2,d3,d4,d5,d6,d7;
            PACK2(d0, a0.x); PACK2(d1, a0.y); PACK2(d2, a0.z); PACK2(d3, a0.w);
            PACK2(d4, a1.x); PACK2(d5, a1.y); PACK2(d6, a1.z); PACK2(d7, a1.w);
            FMA2(acc[ 0], d0, b01.x, acc[ 0]); FMA2(acc[ 1], d0, b01.y, acc[ 1]);
            FMA2(acc[ 2], d0, b23.x, acc[ 2]); FMA2(acc[ 3], d0, b23.y, acc[ 3]);
            FMA2(acc[ 4], d1, b01.x, acc[ 4]); FMA2(acc[ 5], d1, b01.y, acc[ 5]);
            FMA2(acc[ 6], d1, b23.x, acc[ 6]); FMA2(acc[ 7], d1, b23.y, acc[ 7]);
            FMA2(acc[ 8], d2, b01.x, acc[ 8]); FMA2(acc[ 9], d2, b01.y, acc[ 9]);
            FMA2(acc[10], d2, b23.x, acc[10]); FMA2(acc[11], d2, b23.y, acc[11]);
            FMA2(acc[12], d3, b01.x, acc[12]); FMA2(acc[13], d3, b01.y, acc[13]);
            FMA2(acc[14], d3, b23.x, acc[14]); FMA2(acc[15], d3, b23.y, acc[15]);
            FMA2(acc[16], d4, b01.x, acc[16]); FMA2(acc[17], d4, b01.y, acc[17]);
            FMA2(acc[18], d4, b23.x, acc[18]); FMA2(acc[19], d4, b23.y, acc[19]);
            FMA2(acc[20], d5, b01.x, acc[20]); FMA2(acc[21], d5, b01.y, acc[21]);
            FMA2(acc[22], d5, b23.x, acc[22]); FMA2(acc[23], d5, b23.y, acc[23]);
            FMA2(acc[24], d6, b01.x, acc[24]); FMA2(acc[25], d6, b01.y, acc[25]);
            FMA2(acc[26], d6, b23.x, acc[26]); FMA2(acc[27], d6, b23.y, acc[27]);
            FMA2(acc[28], d7, b01.x, acc[28]); FMA2(acc[29], d7, b01.y, acc[29]);
            FMA2(acc[30], d7, b23.x, acc[30]); FMA2(acc[31], d7, b23.y, acc[31]);
        }
    }
    __syncthreads();   // all reads of act + wsm(W1) complete

    // relu + transposed writeback (2x STS.128 per output column); stage W2
#pragma unroll
    for (int oj = 0; oj < 4; oj++){
        float lo[8], hi[8];
#pragma unroll
        for (int mi = 0; mi < 8; mi++) UNPACK2(lo[mi], hi[mi], acc[mi*4 + oj]);
        float4 vl0 = { fmaxf(lo[0],0.f), fmaxf(lo[1],0.f), fmaxf(lo[2],0.f), fmaxf(lo[3],0.f) };
        float4 vl1 = { fmaxf(lo[4],0.f), fmaxf(lo[5],0.f), fmaxf(lo[6],0.f), fmaxf(lo[7],0.f) };
        float4 vh0 = { fmaxf(hi[0],0.f), fmaxf(hi[1],0.f), fmaxf(hi[2],0.f), fmaxf(hi[3],0.f) };
        float4 vh1 = { fmaxf(hi[4],0.f), fmaxf(hi[5],0.f), fmaxf(hi[6],0.f), fmaxf(hi[7],0.f) };
        *(float4*)(act + (o0 + 2*oj    )*128 + m0    ) = vl0;
        *(float4*)(act + (o0 + 2*oj    )*128 + m0 + 4) = vl1;
        *(float4*)(act + (o0 + 2*oj + 1)*128 + m0    ) = vh0;
        *(float4*)(act + (o0 + 2*oj + 1)*128 + m0 + 4) = vh1;
    }
    {
        const float4* src = (const float4*)g_W2t;
        float4* dst = (float4*)wsm;
#pragma unroll
        for (int i = 0; i < 8; i++) dst[tid + i*128] = __ldg(src + tid + i*128);
    }
    __syncthreads();   // layer-1 activations + W2 ready

    // ===== layer 2 =====
    {
        const u64* tp = (const u64*)(g_t2 + o0);
        u64 t0p = tp[0], t1p = tp[1], t2p = tp[2], t3p = tp[3];
#pragma unroll
        for (int mi = 0; mi < 8; mi++){
            acc[mi*4+0]=t0p; acc[mi*4+1]=t1p; acc[mi*4+2]=t2p; acc[mi*4+3]=t3p;
        }
        const float* W = wsm + o0;
#pragma unroll 4
        for (int c = 0; c < 64; c++){
            float4 a0 = *(const float4*)(act + c*128 + m0);
            float4 a1 = *(const float4*)(act + c*128 + m0 + 4);
            ulonglong2 b01 = *(const ulonglong2*)(W + c*64);
            ulonglong2 b23 = *(const ulonglong2*)(W + c*64 + 4);
            u64 d0,d1,d2,d3,d4,d5,d6,d7;
            PACK2(d0, a0.x); PACK2(d1, a0.y); PACK2(d2, a0.z); PACK2(d3, a0.w);
            PACK2(d4, a1.x); PACK2(d5, a1.y); PACK2(d6, a1.z); PACK2(d7, a1.w);
            FMA2(acc[ 0], d0, b01.x, acc[ 0]); FMA2(acc[ 1], d0, b01.y, acc[ 1]);
            FMA2(acc[ 2], d0, b23.x, acc[ 2]); FMA2(acc[ 3], d0, b23.y, acc[ 3]);
            FMA2(acc[ 4], d1, b01.x, acc[ 4]); FMA2(acc[ 5], d1, b01.y, acc[ 5]);
            FMA2(acc[ 6], d1, b23.x, acc[ 6]); FMA2(acc[ 7], d1, b23.y, acc[ 7]);
            FMA2(acc[ 8], d2, b01.x, acc[ 8]); FMA2(acc[ 9], d2, b01.y, acc[ 9]);
            FMA2(acc[10], d2, b23.x, acc[10]); FMA2(acc[11], d2, b23.y, acc[11]);
            FMA2(acc[12], d3, b01.x, acc[12]); FMA2(acc[13], d3, b01.y, acc[13]);
            FMA2(acc[14], d3, b23.x, acc[14]); FMA2(acc[15], d3, b23.y, acc[15]);
            FMA2(acc[16], d4, b01.x, acc[16]); FMA2(acc[17], d4, b01.y, acc[17]);
            FMA2(acc[18], d4, b23.x, acc[18]); FMA2(acc[19], d4, b23.y, acc[19]);
            FMA2(acc[20], d5, b01.x, acc[20]); FMA2(acc[21], d5, b01.y, acc[21]);
            FMA2(acc[22], d5, b23.x, acc[22]); FMA2(acc[23], d5, b23.y, acc[23]);
            FMA2(acc[24], d6, b01.x, acc[24]); FMA2(acc[25], d6, b01.y, acc[25]);
            FMA2(acc[26], d6, b23.x, acc[26]); FMA2(acc[27], d6, b23.y, acc[27]);
            FMA2(acc[28], d7, b01.x, acc[28]); FMA2(acc[29], d7, b01.y, acc[29]);
            FMA2(acc[30], d7, b23.x, acc[30]); FMA2(acc[31], d7, b23.y, acc[31]);
        }
    }
    __syncthreads();   // all reads of act complete (part overlaps act)

    // ===== epilogue: relu + masked per-8-row-group partials =====
    {
        float vf[8];
#pragma unroll
        for (int mi = 0; mi < 8; mi++) vf[mi] = validf[m0 + mi];
#pragma unroll
        for (int oj = 0; oj < 4; oj++){
            float slo = 0.f, shi = 0.f;
#pragma unroll
            for (int mi = 0; mi < 8; mi++){
                float lo, hi;
                UNPACK2(lo, hi, acc[mi*4 + oj]);
                slo += fmaxf(lo, 0.f)*vf[mi];
                shi += fmaxf(hi, 0.f)*vf[mi];
            }
            part[mt*64 + o0 + 2*oj    ] = slo;
            part[mt*64 + o0 + 2*oj + 1] = shi;
        }
    }
    __syncthreads();

    // ===== final: 2-group sum + mean + shortcut + relu =====
#pragma unroll
    for (int s = 0; s < 4; s++){
        const int idx = tid + s*128;        // 512 outputs: 8 points x 64 ch
        const int o   = idx >> 3;
        const int pl  = idx & 7;
        const int pt  = pt0 + pl;
        const int p   = pt & (NP-1);
        float sum = part[(pl*2+0)*64 + o] + part[(pl*2+1)*64 + o];
        float denom = fmaxf(vcnt[pl], 1e-8f);
        float res = fmaxf(sum/denom + g_SC[(size_t)pt*64 + o], 0.f);
        out[((size_t)n*64 + o)*NP + p] = res;
    }
}

// ---------------- launch ----------------
extern "C" void kernel_launch(void* const* d_in, const int* in_sizes, int n_in,
                              void* d_out, int out_size)
{
    const float* feats = (const float*)d_in[0];
    const unsigned char* mask = (const unsigned char*)d_in[1];
    const float* W0 = (const float*)d_in[2];
    const float* W1 = (const float*)d_in[3];
    const float* W2 = (const float*)d_in[4];
    const float* Ws = (const float*)d_in[5];

    cudaFuncSetAttribute(edge_kernel, cudaFuncAttributeMaxDynamicSharedMemorySize, SM_TOTAL);

    fold_kernel<<<16, 256>>>(W0, W1, W2, Ws,
        (const float*)d_in[6],  (const float*)d_in[7],  (const float*)d_in[8],  (const float*)d_in[9],
        (const float*)d_in[10], (const float*)d_in[11], (const float*)d_in[12], (const float*)d_in[13],
        (const float*)d_in[14], (const float*)d_in[15], (const float*)d_in[16], (const float*)d_in[17],
        (const float*)d_in[18], (const float*)d_in[19], (const float*)d_in[20], (const float*)d_in[21]);

    prep_kernel<<<NB*NP/4, 256>>>(feats, mask);
    knn_kernel<<<NB*128, 256>>>(feats, mask);
    edge_kernel<<<NB*NP/8, 128, SM_TOTAL>>>((float*)d_out);
}

// round 13
// speedup vs baseline: 1.5259x; 1.0190x over previous
#include <cuda_runtime.h>

#define NB 64
#define NP 1024
#define CF 16
#define KK 16
#define BN_EPS 1e-5f
#define PITCH 132            // act row pitch in floats (bank-spread padding)

typedef unsigned long long u64;

#define FMA2(d, a, b, c) \
    asm("fma.rn.f32x2 %0, %1, %2, %3;" : "=l"(d) : "l"(a), "l"(b), "l"(c))
#define PACK2(d, x) \
    asm("mov.b64 %0, {%1, %1};" : "=l"(d) : "f"(x))
#define UNPACK2(lo, hi, v) \
    asm("mov.b64 {%0, %1}, %2;" : "=f"(lo), "=f"(hi) : "l"(v))

// ---------------- static scratch (no allocations allowed) ----------------
__device__ float g_C [NB*NP*64];
__device__ float g_Y [NB*NP*64];
__device__ float g_SC[NB*NP*64];
__device__ int   g_idx[NB*NP*KK];
__device__ int   g_valid[NB];
__device__ float g_W1t[64*64];     // W1 (BN-scaled), TRANSPOSED [c][o]
__device__ float g_W2t[64*64];
__device__ float g_W0at[CF*64], g_W0bt[CF*64], g_Wst[CF*64];
__device__ float g_t0[64], g_t1[64], g_t2[64], g_ts[64];

// ---------------- fold BN into weights / biases ----------------
__global__ void fold_kernel(const float* __restrict__ W0, const float* __restrict__ W1,
    const float* __restrict__ W2, const float* __restrict__ Ws,
    const float* g0,const float* b0,const float* m0,const float* v0,
    const float* g1,const float* b1,const float* m1,const float* v1,
    const float* g2,const float* b2,const float* m2,const float* v2,
    const float* gs,const float* bs,const float* ms,const float* vs)
{
    int t = blockIdx.x*blockDim.x + threadIdx.x;
    if (t < 64){
        float s0 = g0[t]*rsqrtf(v0[t]+BN_EPS); g_t0[t]=b0[t]-m0[t]*s0;
        float s1 = g1[t]*rsqrtf(v1[t]+BN_EPS); g_t1[t]=b1[t]-m1[t]*s1;
        float s2 = g2[t]*rsqrtf(v2[t]+BN_EPS); g_t2[t]=b2[t]-m2[t]*s2;
        float ss = gs[t]*rsqrtf(vs[t]+BN_EPS); g_ts[t]=bs[t]-ms[t]*ss;
    }
    if (t < 1024){
        int o = t >> 4, c = t & 15;
        float s0 = g0[o]*rsqrtf(v0[o]+BN_EPS);
        float ss = gs[o]*rsqrtf(vs[o]+BN_EPS);
        float wa = W0[o*32 + c], wb = W0[o*32 + 16 + c];
        g_W0at[c*64 + o] = (wa + wb)*s0;
        g_W0bt[c*64 + o] = wb*s0;
        g_Wst [c*64 + o] = Ws[o*16 + c]*ss;
    }
    if (t < 4096){
        int oo = t >> 6, cc = t & 63;
        g_W1t[cc*64 + oo] = W1[t]*(g1[oo]*rsqrtf(v1[oo]+BN_EPS));
        g_W2t[cc*64 + oo] = W2[t]*(g2[oo]*rsqrtf(v2[oo]+BN_EPS));
    }
}

// ---------------- KNN + fused prep: warp-per-point bitonic ----------------
__global__ void __launch_bounds__(256)
knn_kernel(const float* __restrict__ feats,
           const unsigned char* __restrict__ mask)
{
    const int n    = blockIdx.x >> 7;
    const int bloc = blockIdx.x & 127;
    const int warp = threadIdx.x >> 5;
    const int lane = threadIdx.x & 31;
    const int p    = bloc*8 + warp;

    __shared__ float px[NP], py[NP], rr[NP];
    __shared__ unsigned int heads[8][512];
    __shared__ float sx[8][CF];
    __shared__ int scnt;

    if (threadIdx.x == 0) scnt = 0;
    int mcnt = 0;
    for (int i = threadIdx.x; i < NP; i += 256){
        float x = feats[(n*NP + i)*(2+CF) + 0];
        float y = feats[(n*NP + i)*(2+CF) + 1];
        px[i] = x; py[i] = y; rr[i] = x*x + y*y;
        if (bloc == 0 && mask[n*NP + i]) mcnt++;
    }
    if (threadIdx.x < 128){
        int lp = threadIdx.x >> 4, c = threadIdx.x & 15;
        sx[lp][c] = feats[(n*NP + bloc*8 + lp)*(2+CF) + 2 + c];
    }
    __syncthreads();
    if (bloc == 0 && mcnt) atomicAdd(&scnt, mcnt);

    const float xp = px[p], yp = py[p], rp = rr[p];
    const float nx = -2.f*xp, ny = -2.f*yp;

    unsigned int key[32];
#pragma unroll
    for (int i = 0; i < 32; i++){
        int q = i*32 + lane;
        float d = fmaxf(fmaf(nx, px[q], fmaf(ny, py[q], rp + rr[q])), 0.f);
        unsigned int kb = (__float_as_uint(d) & 0xFFFFFC00u) | (unsigned int)q;
        key[i] = (q == p) ? 0xFFFFFFFFu : kb;
    }
#pragma unroll
    for (int kk = 2; kk <= 32; kk <<= 1){
#pragma unroll
        for (int j = kk >> 1; j > 0; j >>= 1){
#pragma unroll
            for (int i = 0; i < 32; i++){
                int l = i ^ j;
                if (l > i){
                    unsigned int a = key[i], b = key[l];
                    unsigned int lo = a < b ? a : b;
                    unsigned int hi = a < b ? b : a;
                    if ((i & kk) == 0){ key[i] = lo; key[l] = hi; }
                    else              { key[i] = hi; key[l] = lo; }
                }
            }
        }
    }
#pragma unroll
    for (int j = 0; j < 16; j++) heads[warp][j*32 + lane] = key[j];

    int ptr = 0;
    unsigned int sel = 0;
#pragma unroll 1
    for (int r = 0; r < KK; r++){
        unsigned int h = (ptr < 16) ? heads[warp][ptr*32 + lane] : 0xFFFFFFFFu;
        unsigned int w = h;
#pragma unroll
        for (int d = 16; d; d >>= 1){
            unsigned int o = __shfl_xor_sync(0xFFFFFFFFu, w, d);
            w = (o < w) ? o : w;
        }
        if (h == w) ptr++;
        if (lane == r) sel = w;
    }
    if (lane < KK) g_idx[(n*NP + p)*KK + lane] = (int)(sel & 1023u);

    // ---- fused prep: per-point projections C, Y, shortcut ----
#pragma unroll
    for (int s = 0; s < 2; s++){
        const int idx = threadIdx.x + s*256;    // 512 = 8 points x 64 ch
        const int lp  = idx >> 6;
        const int o   = idx & 63;
        float a = 0.f, yb = 0.f, sc = 0.f;
#pragma unroll
        for (int c = 0; c < CF; c++){
            float x = sx[lp][c];
            a  = fmaf(x, g_W0at[c*64 + o], a);
            yb = fmaf(x, g_W0bt[c*64 + o], yb);
            sc = fmaf(x, g_Wst [c*64 + o], sc);
        }
        const int pt = n*NP + bloc*8 + lp;
        g_C[(size_t)pt*64 + o] = a + g_t0[o];
        g_Y[(size_t)pt*64 + o] = yb;
        float scv = sc + g_ts[o];
        if (mask[pt]) scv = 0.f;
        g_SC[(size_t)pt*64 + o] = scv;
    }

    if (bloc == 0){
        __syncthreads();
        if (threadIdx.x == 0) g_valid[n] = NP - scnt;
    }
}

// ---------------- edge kernel v10: coalesced gather + 8Mx8N SMEM-weight GEMM ----------------
// Phase 0: half-warp-per-row Y/C gather (4 wf per LDG.128 vs 32 for the old
// lane-per-row pattern); act pitch 132 spreads the STS.32 scatter across banks.
// Mainloop identical to R12 (best): 8Mx8N thread tile, SMEM-staged weights.
#define SM_ACT    0                    // 64*132 floats = 33792 B (part overlaps)
#define SM_W      33792                // 64*64 floats = 16384 B
#define SM_VALIDF 50176                // 128 floats
#define SM_VCNT   50688                // 8 floats
#define SM_TOTAL  50720

__global__ void __launch_bounds__(128)
edge_kernel(float* __restrict__ out)
{
    extern __shared__ char smraw[];
    float* act    = (float*)(smraw + SM_ACT);
    float* wsm    = (float*)(smraw + SM_W);
    float* part   = (float*)(smraw + SM_ACT);     // overlaps act (used after L2)
    float* validf = (float*)(smraw + SM_VALIDF);
    float* vcnt   = (float*)(smraw + SM_VCNT);

    const int tid  = threadIdx.x;
    const int lane = tid & 31;
    const int w    = tid >> 5;
    const int pt0  = blockIdx.x * 8;
    const int n    = pt0 >> 10;

    const int valid = g_valid[n];

    // ---- stage W1 ----
    {
        const float4* src = (const float4*)g_W1t;
        float4* dst = (float4*)wsm;
#pragma unroll
        for (int i = 0; i < 8; i++) dst[tid + i*128] = __ldg(src + tid + i*128);
    }

    // ---- phase 0: coalesced Y/C gather, layer-0 activations into act[c][m] ----
    {
        const int half  = lane >> 4;       // which edge of the pair
        const int chunk = lane & 15;       // float4 index within the 64-ch row
#pragma unroll 4
        for (int i = 0; i < 16; i++){
            const int e  = w*32 + i*2 + half;
            const int pt = pt0 + (e >> 4);
            const int q  = __ldg(&g_idx[pt*KK + (e & 15)]);
            if (chunk == 0) validf[e] = (q < valid) ? 1.f : 0.f;
            float4 y  = __ldg((const float4*)(g_Y + ((size_t)n*NP + q)*64) + chunk);
            float4 c4 = __ldg((const float4*)(g_C + (size_t)pt*64) + chunk);
            const int cc = chunk*4;
            act[(cc+0)*PITCH + e] = fmaxf(c4.x - y.x, 0.f);
            act[(cc+1)*PITCH + e] = fmaxf(c4.y - y.y, 0.f);
            act[(cc+2)*PITCH + e] = fmaxf(c4.z - y.z, 0.f);
            act[(cc+3)*PITCH + e] = fmaxf(c4.w - y.w, 0.f);
        }
    }
    __syncthreads();

    if (tid < 8){
        float s = 0.f;
#pragma unroll
        for (int j = 0; j < 16; j++) s += validf[tid*16 + j];
        vcnt[tid] = s;
    }

    // ---- tiling: 16 M-tiles x 8 N-tiles; thread = 8M x 8N ----
    const int mt = tid & 15;
    const int nt = tid >> 4;
    const int m0 = mt * 8;
    const int o0 = nt * 8;

    u64 acc[32];   // acc[mi*4 + oj] = packed (o0+2oj, o0+2oj+1) for row m0+mi

    // ===== layer 1 =====
    {
        const u64* tp = (const u64*)(g_t1 + o0);
        u64 t0p = tp[0], t1p = tp[1], t2p = tp[2], t3p = tp[3];
#pragma unroll
        for (int mi = 0; mi < 8; mi++){
            acc[mi*4+0]=t0p; acc[mi*4+1]=t1p; acc[mi*4+2]=t2p; acc[mi*4+3]=t3p;
        }
        const float* W = wsm + o0;
#pragma unroll 4
        for (int c = 0; c < 64; c++){
            float4 a0 = *(const float4*)(act + c*PITCH + m0);
            float4 a1 = *(const float4*)(act + c*PITCH + m0 + 4);
            ulonglong2 b01 = *(const ulonglong2*)(W + c*64);
            ulonglong2 b23 = *(const ulonglong2*)(W + c*64 + 4);
            u64 d0,d1,d2,d3,d4,d5,d6,d7;
            PACK2(d0, a0.x); PACK2(d1, a0.y); PACK2(d2, a0.z); PACK2(d3, a0.w);
            PACK2(d4, a1.x); PACK2(d5, a1.y); PACK2(d6, a1.z); PACK2(d7, a1.w);
            FMA2(acc[ 0], d0, b01.x, acc[ 0]); FMA2(acc[ 1], d0, b01.y, acc[ 1]);
            FMA2(acc[ 2], d0, b23.x, acc[ 2]); FMA2(acc[ 3], d0, b23.y, acc[ 3]);
            FMA2(acc[ 4], d1, b01.x, acc[ 4]); FMA2(acc[ 5], d1, b01.y, acc[ 5]);
            FMA2(acc[ 6], d1, b23.x, acc[ 6]); FMA2(acc[ 7], d1, b23.y, acc[ 7]);
            FMA2(acc[ 8], d2, b01.x, acc[ 8]); FMA2(acc[ 9], d2, b01.y, acc[ 9]);
            FMA2(acc[10], d2, b23.x, acc[10]); FMA2(acc[11], d2, b23.y, acc[11]);
            FMA2(acc[12], d3, b01.x, acc[12]); FMA2(acc[13], d3, b01.y, acc[13]);
            FMA2(acc[14], d3, b23.x, acc[14]); FMA2(acc[15], d3, b23.y, acc[15]);
            FMA2(acc[16], d4, b01.x, acc[16]); FMA2(acc[17], d4, b01.y, acc[17]);
            FMA2(acc[18], d4, b23.x, acc[18]); FMA2(acc[19], d4, b23.y, acc[19]);
            FMA2(acc[20], d5, b01.x, acc[20]); FMA2(acc[21], d5, b01.y, acc[21]);
            FMA2(acc[22], d5, b23.x, acc[22]); FMA2(acc[23], d5, b23.y, acc[23]);
            FMA2(acc[24], d6, b01.x, acc[24]); FMA2(acc[25], d6, b01.y, acc[25]);
            FMA2(acc[26], d6, b23.x, acc[26]); FMA2(acc[27], d6, b23.y, acc[27]);
            FMA2(acc[28], d7, b01.x, acc[28]); FMA2(acc[29], d7, b01.y, acc[29]);
            FMA2(acc[30], d7, b23.x, acc[30]); FMA2(acc[31], d7, b23.y, acc[31]);
        }
    }
    __syncthreads();   // all reads of act + wsm(W1) complete

    // relu + transposed writeback; stage W2
#pragma unroll
    for (int oj = 0; oj < 4; oj++){
        float lo[8], hi[8];
#pragma unroll
        for (int mi = 0; mi < 8; mi++) UNPACK2(lo[mi], hi[mi], acc[mi*4 + oj]);
        float4 vl0 = { fmaxf(lo[0],0.f), fmaxf(lo[1],0.f), fmaxf(lo[2],0.f), fmaxf(lo[3],0.f) };
        float4 vl1 = { fmaxf(lo[4],0.f), fmaxf(lo[5],0.f), fmaxf(lo[6],0.f), fmaxf(lo[7],0.f) };
        float4 vh0 = { fmaxf(hi[0],0.f), fmaxf(hi[1],0.f), fmaxf(hi[2],0.f), fmaxf(hi[3],0.f) };
        float4 vh1 = { fmaxf(hi[4],0.f), fmaxf(hi[5],0.f), fmaxf(hi[6],0.f), fmaxf(hi[7],0.f) };
        *(float4*)(act + (o0 + 2*oj    )*PITCH + m0    ) = vl0;
        *(float4*)(act + (o0 + 2*oj    )*PITCH + m0 + 4) = vl1;
        *(float4*)(act + (o0 + 2*oj + 1)*PITCH + m0    ) = vh0;
        *(float4*)(act + (o0 + 2*oj + 1)*PITCH + m0 + 4) = vh1;
    }
    {
        const float4* src = (const float4*)g_W2t;
        float4* dst = (float4*)wsm;
#pragma unroll
        for (int i = 0; i < 8; i++) dst[tid + i*128] = __ldg(src + tid + i*128);
    }
    __syncthreads();   // layer-1 activations + W2 ready

    // ===== layer 2 =====
    {
        const u64* tp = (const u64*)(g_t2 + o0);
        u64 t0p = tp[0], t1p = tp[1], t2p = tp[2], t3p = tp[3];
#pragma unroll
        for (int mi = 0; mi < 8; mi++){
            acc[mi*4+0]=t0p; acc[mi*4+1]=t1p; acc[mi*4+2]=t2p; acc[mi*4+3]=t3p;
        }
        const float* W = wsm + o0;
#pragma unroll 4
        for (int c = 0; c < 64; c++){
            float4 a0 = *(const float4*)(act + c*PITCH + m0);
            float4 a1 = *(const float4*)(act + c*PITCH + m0 + 4);
            ulonglong2 b01 = *(const ulonglong2*)(W + c*64);
            ulonglong2 b23 = *(const ulonglong2*)(W + c*64 + 4);
            u64 d0,d1,d2,d3,d4,d5,d6,d7;
            PACK2(d0, a0.x); PACK2(d1, a0.y); PACK2(d2, a0.z); PACK2(d3, a0.w);
            PACK2(d4, a1.x); PACK2(d5, a1.y); PACK2(d6, a1.z); PACK2(d7, a1.w);
            FMA2(acc[ 0], d0, b01.x, acc[ 0]); FMA2(acc[ 1], d0, b01.y, acc[ 1]);
            FMA2(acc[ 2], d0, b23.x, acc[ 2]); FMA2(acc[ 3], d0, b23.y, acc[ 3]);
            FMA2(acc[ 4], d1, b01.x, acc[ 4]); FMA2(acc[ 5], d1, b01.y, acc[ 5]);
            FMA2(acc[ 6], d1, b23.x, acc[ 6]); FMA2(acc[ 7], d1, b23.y, acc[ 7]);
            FMA2(acc[ 8], d2, b01.x, acc[ 8]); FMA2(acc[ 9], d2, b01.y, acc[ 9]);
            FMA2(acc[10], d2, b23.x, acc[10]); FMA2(acc[11], d2, b23.y, acc[11]);
            FMA2(acc[12], d3, b01.x, acc[12]); FMA2(acc[13], d3, b01.y, acc[13]);
            FMA2(acc[14], d3, b23.x, acc[14]); FMA2(acc[15], d3, b23.y, acc[15]);
            FMA2(acc[16], d4, b01.x, acc[16]); FMA2(acc[17], d4, b01.y, acc[17]);
            FMA2(acc[18], d4, b23.x, acc[18]); FMA2(acc[19], d4, b23.y, acc[19]);
            FMA2(acc[20], d5, b01.x, acc[20]); FMA2(acc[21], d5, b01.y, acc[21]);
            FMA2(acc[22], d5, b23.x, acc[22]); FMA2(acc[23], d5, b23.y, acc[23]);
            FMA2(acc[24], d6, b01.x, acc[24]); FMA2(acc[25], d6, b01.y, acc[25]);
            FMA2(acc[26], d6, b23.x, acc[26]); FMA2(acc[27], d6, b23.y, acc[27]);
            FMA2(acc[28], d7, b01.x, acc[28]); FMA2(acc[29], d7, b01.y, acc[29]);
            FMA2(acc[30], d7, b23.x, acc[30]); FMA2(acc[31], d7, b23.y, acc[31]);
        }
    }
    __syncthreads();   // all reads of act complete (part overlaps act)

    // ===== epilogue: relu + masked per-8-row-group partials =====
    {
        float vf[8];
#pragma unroll
        for (int mi = 0; mi < 8; mi++) vf[mi] = validf[m0 + mi];
#pragma unroll
        for (int oj = 0; oj < 4; oj++){
            float slo = 0.f, shi = 0.f;
#pragma unroll
            for (int mi = 0; mi < 8; mi++){
                float lo, hi;
                UNPACK2(lo, hi, acc[mi*4 + oj]);
                slo += fmaxf(lo, 0.f)*vf[mi];
                shi += fmaxf(hi, 0.f)*vf[mi];
            }
            part[mt*64 + o0 + 2*oj    ] = slo;
            part[mt*64 + o0 + 2*oj + 1] = shi;
        }
    }
    __syncthreads();

    // ===== final: 2-group sum + mean + shortcut + relu =====
#pragma unroll
    for (int s = 0; s < 4; s++){
        const int idx = tid + s*128;        // 512 outputs: 8 points x 64 ch
        const int o   = idx >> 3;
        const int pl  = idx & 7;
        const int pt  = pt0 + pl;
        const int p   = pt & (NP-1);
        float sum = part[(pl*2+0)*64 + o] + part[(pl*2+1)*64 + o];
        float denom = fmaxf(vcnt[pl], 1e-8f);
        float res = fmaxf(sum/denom + g_SC[(size_t)pt*64 + o], 0.f);
        out[((size_t)n*64 + o)*NP + p] = res;
    }
}

// ---------------- launch ----------------
extern "C" void kernel_launch(void* const* d_in, const int* in_sizes, int n_in,
                              void* d_out, int out_size)
{
    const float* feats = (const float*)d_in[0];
    const unsigned char* mask = (const unsigned char*)d_in[1];
    const float* W0 = (const float*)d_in[2];
    const float* W1 = (const float*)d_in[3];
    const float* W2 = (const float*)d_in[4];
    const float* Ws = (const float*)d_in[5];

    cudaFuncSetAttribute(edge_kernel, cudaFuncAttributeMaxDynamicSharedMemorySize, SM_TOTAL);

    fold_kernel<<<16, 256>>>(W0, W1, W2, Ws,
        (const float*)d_in[6],  (const float*)d_in[7],  (const float*)d_in[8],  (const float*)d_in[9],
        (const float*)d_in[10], (const float*)d_in[11], (const float*)d_in[12], (const float*)d_in[13],
        (const float*)d_in[14], (const float*)d_in[15], (const float*)d_in[16], (const float*)d_in[17],
        (const float*)d_in[18], (const float*)d_in[19], (const float*)d_in[20], (const float*)d_in[21]);

    knn_kernel<<<NB*128, 256>>>(feats, mask);
    edge_kernel<<<NB*NP/8, 128, SM_TOTAL>>>((float*)d_out);
}

// round 14
// speedup vs baseline: 1.5890x; 1.0413x over previous
#include <cuda_runtime.h>

#define NB 64
#define NP 1024
#define CF 16
#define KK 16
#define BN_EPS 1e-5f

typedef unsigned long long u64;

#define FMA2(d, a, b, c) \
    asm("fma.rn.f32x2 %0, %1, %2, %3;" : "=l"(d) : "l"(a), "l"(b), "l"(c))
#define PACK2(d, x) \
    asm("mov.b64 %0, {%1, %1};" : "=l"(d) : "f"(x))
#define UNPACK2(lo, hi, v) \
    asm("mov.b64 {%0, %1}, %2;" : "=f"(lo), "=f"(hi) : "l"(v))

// act XOR swizzle: 8-granular, spreads phase-0 scatter across 4x banks.
#define SW(c) ((((c) >> 2) & 3) << 3)

// ---------------- static scratch (no allocations allowed) ----------------
__device__ float g_C [NB*NP*64];
__device__ float g_Y [NB*NP*64];
__device__ float g_SC[NB*NP*64];
__device__ int   g_idx[NB*NP*KK];
__device__ int   g_valid[NB];
__device__ float g_W1t[64*64];     // W1 (BN-scaled), TRANSPOSED [c][o]
__device__ float g_W2t[64*64];
__device__ float g_W0at[CF*64], g_W0bt[CF*64], g_Wst[CF*64];
__device__ float g_t0[64], g_t1[64], g_t2[64], g_ts[64];

// ---------------- fold BN into weights / biases ----------------
__global__ void fold_kernel(const float* __restrict__ W0, const float* __restrict__ W1,
    const float* __restrict__ W2, const float* __restrict__ Ws,
    const float* g0,const float* b0,const float* m0,const float* v0,
    const float* g1,const float* b1,const float* m1,const float* v1,
    const float* g2,const float* b2,const float* m2,const float* v2,
    const float* gs,const float* bs,const float* ms,const float* vs)
{
    int t = blockIdx.x*blockDim.x + threadIdx.x;
    if (t < 64){
        float s0 = g0[t]*rsqrtf(v0[t]+BN_EPS); g_t0[t]=b0[t]-m0[t]*s0;
        float s1 = g1[t]*rsqrtf(v1[t]+BN_EPS); g_t1[t]=b1[t]-m1[t]*s1;
        float s2 = g2[t]*rsqrtf(v2[t]+BN_EPS); g_t2[t]=b2[t]-m2[t]*s2;
        float ss = gs[t]*rsqrtf(vs[t]+BN_EPS); g_ts[t]=bs[t]-ms[t]*ss;
    }
    if (t < 1024){
        int o = t >> 4, c = t & 15;
        float s0 = g0[o]*rsqrtf(v0[o]+BN_EPS);
        float ss = gs[o]*rsqrtf(vs[o]+BN_EPS);
        float wa = W0[o*32 + c], wb = W0[o*32 + 16 + c];
        g_W0at[c*64 + o] = (wa + wb)*s0;
        g_W0bt[c*64 + o] = wb*s0;
        g_Wst [c*64 + o] = Ws[o*16 + c]*ss;
    }
    if (t < 4096){
        int oo = t >> 6, cc = t & 63;
        g_W1t[cc*64 + oo] = W1[t]*(g1[oo]*rsqrtf(v1[oo]+BN_EPS));
        g_W2t[cc*64 + oo] = W2[t]*(g2[oo]*rsqrtf(v2[oo]+BN_EPS));
    }
}

// ---------------- KNN + fused prep: warp-per-point bitonic ----------------
__global__ void __launch_bounds__(256)
knn_kernel(const float* __restrict__ feats,
           const unsigned char* __restrict__ mask)
{
    const int n    = blockIdx.x >> 7;
    const int bloc = blockIdx.x & 127;
    const int warp = threadIdx.x >> 5;
    const int lane = threadIdx.x & 31;
    const int p    = bloc*8 + warp;

    __shared__ float px[NP], py[NP], rr[NP];
    __shared__ unsigned int heads[8][512];
    __shared__ float sx[8][CF];
    __shared__ int scnt;

    if (threadIdx.x == 0) scnt = 0;
    int mcnt = 0;
    for (int i = threadIdx.x; i < NP; i += 256){
        float x = feats[(n*NP + i)*(2+CF) + 0];
        float y = feats[(n*NP + i)*(2+CF) + 1];
        px[i] = x; py[i] = y; rr[i] = x*x + y*y;
        if (bloc == 0 && mask[n*NP + i]) mcnt++;
    }
    if (threadIdx.x < 128){
        int lp = threadIdx.x >> 4, c = threadIdx.x & 15;
        sx[lp][c] = feats[(n*NP + bloc*8 + lp)*(2+CF) + 2 + c];
    }
    __syncthreads();
    if (bloc == 0 && mcnt) atomicAdd(&scnt, mcnt);

    const float xp = px[p], yp = py[p], rp = rr[p];
    const float nx = -2.f*xp, ny = -2.f*yp;

    unsigned int key[32];
#pragma unroll
    for (int i = 0; i < 32; i++){
        int q = i*32 + lane;
        float d = fmaxf(fmaf(nx, px[q], fmaf(ny, py[q], rp + rr[q])), 0.f);
        unsigned int kb = (__float_as_uint(d) & 0xFFFFFC00u) | (unsigned int)q;
        key[i] = (q == p) ? 0xFFFFFFFFu : kb;
    }
#pragma unroll
    for (int kk = 2; kk <= 32; kk <<= 1){
#pragma unroll
        for (int j = kk >> 1; j > 0; j >>= 1){
#pragma unroll
            for (int i = 0; i < 32; i++){
                int l = i ^ j;
                if (l > i){
                    unsigned int a = key[i], b = key[l];
                    unsigned int lo = a < b ? a : b;
                    unsigned int hi = a < b ? b : a;
                    if ((i & kk) == 0){ key[i] = lo; key[l] = hi; }
                    else              { key[i] = hi; key[l] = lo; }
                }
            }
        }
    }
#pragma unroll
    for (int j = 0; j < 16; j++) heads[warp][j*32 + lane] = key[j];

    int ptr = 0;
    unsigned int sel = 0;
#pragma unroll 1
    for (int r = 0; r < KK; r++){
        unsigned int h = (ptr < 16) ? heads[warp][ptr*32 + lane] : 0xFFFFFFFFu;
        unsigned int w = h;
#pragma unroll
        for (int d = 16; d; d >>= 1){
            unsigned int o = __shfl_xor_sync(0xFFFFFFFFu, w, d);
            w = (o < w) ? o : w;
        }
        if (h == w) ptr++;
        if (lane == r) sel = w;
    }
    if (lane < KK) g_idx[(n*NP + p)*KK + lane] = (int)(sel & 1023u);

    // ---- fused prep: per-point projections C, Y, shortcut ----
#pragma unroll
    for (int s = 0; s < 2; s++){
        const int idx = threadIdx.x + s*256;
        const int lp  = idx >> 6;
        const int o   = idx & 63;
        float a = 0.f, yb = 0.f, sc = 0.f;
#pragma unroll
        for (int c = 0; c < CF; c++){
            float x = sx[lp][c];
            a  = fmaf(x, g_W0at[c*64 + o], a);
            yb = fmaf(x, g_W0bt[c*64 + o], yb);
            sc = fmaf(x, g_Wst [c*64 + o], sc);
        }
        const int pt = n*NP + bloc*8 + lp;
        g_C[(size_t)pt*64 + o] = a + g_t0[o];
        g_Y[(size_t)pt*64 + o] = yb;
        float scv = sc + g_ts[o];
        if (mask[pt]) scv = 0.f;
        g_SC[(size_t)pt*64 + o] = scv;
    }

    if (bloc == 0){
        __syncthreads();
        if (threadIdx.x == 0) g_valid[n] = NP - scnt;
    }
}

// ---------------- edge kernel v11: XOR-swizzled act + 8Mx8N SMEM-weight GEMM ----------------
// act[c][m] at c*128 + (m ^ SW(c)): phase-0 scatter drops from 8/16-way to
// 4-way bank conflicts; mainloop float4 reads stay aligned (SW is 8-granular)
// and conflict-free; writeback uses the same formula.
#define SM_ACT    0                    // 64*128 floats = 32768 B (part overlaps)
#define SM_W      32768                // 64*64 floats = 16384 B
#define SM_VALIDF 49152                // 128 floats
#define SM_VCNT   49664                // 8 floats
#define SM_TOTAL  49696

__global__ void __launch_bounds__(128)
edge_kernel(float* __restrict__ out)
{
    extern __shared__ char smraw[];
    float* act    = (float*)(smraw + SM_ACT);
    float* wsm    = (float*)(smraw + SM_W);
    float* part   = (float*)(smraw + SM_ACT);     // overlaps act (used after L2)
    float* validf = (float*)(smraw + SM_VALIDF);
    float* vcnt   = (float*)(smraw + SM_VCNT);

    const int tid  = threadIdx.x;
    const int lane = tid & 31;
    const int w    = tid >> 5;
    const int pt0  = blockIdx.x * 8;
    const int n    = pt0 >> 10;

    const int valid = g_valid[n];

    // ---- stage W1 ----
    {
        const float4* src = (const float4*)g_W1t;
        float4* dst = (float4*)wsm;
#pragma unroll
        for (int i = 0; i < 8; i++) dst[tid + i*128] = __ldg(src + tid + i*128);
    }

    // ---- phase 0: coalesced Y/C gather, swizzled scatter into act ----
    {
        const int half  = lane >> 4;       // which edge of the pair
        const int chunk = lane & 15;       // float4 index within the 64-ch row
        const int sw    = (chunk & 3) << 3;  // == SW(chunk*4 + j) for j<4
#pragma unroll 4
        for (int i = 0; i < 16; i++){
            const int e  = w*32 + i*2 + half;
            const int pt = pt0 + (e >> 4);
            const int q  = __ldg(&g_idx[pt*KK + (e & 15)]);
            if (chunk == 0) validf[e] = (q < valid) ? 1.f : 0.f;
            float4 y  = __ldg((const float4*)(g_Y + ((size_t)n*NP + q)*64) + chunk);
            float4 c4 = __ldg((const float4*)(g_C + (size_t)pt*64) + chunk);
            const int cc = chunk*4;
            const int es = e ^ sw;
            act[(cc+0)*128 + es] = fmaxf(c4.x - y.x, 0.f);
            act[(cc+1)*128 + es] = fmaxf(c4.y - y.y, 0.f);
            act[(cc+2)*128 + es] = fmaxf(c4.z - y.z, 0.f);
            act[(cc+3)*128 + es] = fmaxf(c4.w - y.w, 0.f);
        }
    }
    __syncthreads();

    if (tid < 8){
        float s = 0.f;
#pragma unroll
        for (int j = 0; j < 16; j++) s += validf[tid*16 + j];
        vcnt[tid] = s;
    }

    // ---- tiling: 16 M-tiles x 8 N-tiles; thread = 8M x 8N ----
    const int mt = tid & 15;
    const int nt = tid >> 4;
    const int m0 = mt * 8;
    const int o0 = nt * 8;

    u64 acc[32];   // acc[mi*4 + oj] = packed (o0+2oj, o0+2oj+1) for row m0+mi

    // ===== layer 1 =====
    {
        const u64* tp = (const u64*)(g_t1 + o0);
        u64 t0p = tp[0], t1p = tp[1], t2p = tp[2], t3p = tp[3];
#pragma unroll
        for (int mi = 0; mi < 8; mi++){
            acc[mi*4+0]=t0p; acc[mi*4+1]=t1p; acc[mi*4+2]=t2p; acc[mi*4+3]=t3p;
        }
        const float* W = wsm + o0;
#pragma unroll 4
        for (int c = 0; c < 64; c++){
            const float* A = act + c*128 + (m0 ^ SW(c));
            float4 a0 = *(const float4*)(A);
            float4 a1 = *(const float4*)(A + 4);
            ulonglong2 b01 = *(const ulonglong2*)(W + c*64);
            ulonglong2 b23 = *(const ulonglong2*)(W + c*64 + 4);
            u64 d0,d1,d2,d3,d4,d5,d6,d7;
            PACK2(d0, a0.x); PACK2(d1, a0.y); PACK2(d2, a0.z); PACK2(d3, a0.w);
            PACK2(d4, a1.x); PACK2(d5, a1.y); PACK2(d6, a1.z); PACK2(d7, a1.w);
            FMA2(acc[ 0], d0, b01.x, acc[ 0]); FMA2(acc[ 1], d0, b01.y, acc[ 1]);
            FMA2(acc[ 2], d0, b23.x, acc[ 2]); FMA2(acc[ 3], d0, b23.y, acc[ 3]);
            FMA2(acc[ 4], d1, b01.x, acc[ 4]); FMA2(acc[ 5], d1, b01.y, acc[ 5]);
            FMA2(acc[ 6], d1, b23.x, acc[ 6]); FMA2(acc[ 7], d1, b23.y, acc[ 7]);
            FMA2(acc[ 8], d2, b01.x, acc[ 8]); FMA2(acc[ 9], d2, b01.y, acc[ 9]);
            FMA2(acc[10], d2, b23.x, acc[10]); FMA2(acc[11], d2, b23.y, acc[11]);
            FMA2(acc[12], d3, b01.x, acc[12]); FMA2(acc[13], d3, b01.y, acc[13]);
            FMA2(acc[14], d3, b23.x, acc[14]); FMA2(acc[15], d3, b23.y, acc[15]);
            FMA2(acc[16], d4, b01.x, acc[16]); FMA2(acc[17], d4, b01.y, acc[17]);
            FMA2(acc[18], d4, b23.x, acc[18]); FMA2(acc[19], d4, b23.y, acc[19]);
            FMA2(acc[20], d5, b01.x, acc[20]); FMA2(acc[21], d5, b01.y, acc[21]);
            FMA2(acc[22], d5, b23.x, acc[22]); FMA2(acc[23], d5, b23.y, acc[23]);
            FMA2(acc[24], d6, b01.x, acc[24]); FMA2(acc[25], d6, b01.y, acc[25]);
            FMA2(acc[26], d6, b23.x, acc[26]); FMA2(acc[27], d6, b23.y, acc[27]);
            FMA2(acc[28], d7, b01.x, acc[28]); FMA2(acc[29], d7, b01.y, acc[29]);
            FMA2(acc[30], d7, b23.x, acc[30]); FMA2(acc[31], d7, b23.y, acc[31]);
        }
    }
    __syncthreads();   // all reads of act + wsm(W1) complete

    // relu + transposed writeback (swizzled); stage W2
#pragma unroll
    for (int oj = 0; oj < 4; oj++){
        float lo[8], hi[8];
#pragma unroll
        for (int mi = 0; mi < 8; mi++) UNPACK2(lo[mi], hi[mi], acc[mi*4 + oj]);
        float4 vl0 = { fmaxf(lo[0],0.f), fmaxf(lo[1],0.f), fmaxf(lo[2],0.f), fmaxf(lo[3],0.f) };
        float4 vl1 = { fmaxf(lo[4],0.f), fmaxf(lo[5],0.f), fmaxf(lo[6],0.f), fmaxf(lo[7],0.f) };
        float4 vh0 = { fmaxf(hi[0],0.f), fmaxf(hi[1],0.f), fmaxf(hi[2],0.f), fmaxf(hi[3],0.f) };
        float4 vh1 = { fmaxf(hi[4],0.f), fmaxf(hi[5],0.f), fmaxf(hi[6],0.f), fmaxf(hi[7],0.f) };
        const int olo = o0 + 2*oj;
        const int ms  = m0 ^ SW(olo);      // SW(olo) == SW(olo+1) (same >>2 group)
        *(float4*)(act + (olo    )*128 + ms    ) = vl0;
        *(float4*)(act + (olo    )*128 + ms + 4) = vl1;
        *(float4*)(act + (olo + 1)*128 + ms    ) = vh0;
        *(float4*)(act + (olo + 1)*128 + ms + 4) = vh1;
    }
    {
        const float4* src = (const float4*)g_W2t;
        float4* dst = (float4*)wsm;
#pragma unroll
        for (int i = 0; i < 8; i++) dst[tid + i*128] = __ldg(src + tid + i*128);
    }
    __syncthreads();   // layer-1 activations + W2 ready

    // ===== layer 2 =====
    {
        const u64* tp = (const u64*)(g_t2 + o0);
        u64 t0p = tp[0], t1p = tp[1], t2p = tp[2], t3p = tp[3];
#pragma unroll
        for (int mi = 0; mi < 8; mi++){
            acc[mi*4+0]=t0p; acc[mi*4+1]=t1p; acc[mi*4+2]=t2p; acc[mi*4+3]=t3p;
        }
        const float* W = wsm + o0;
#pragma unroll 4
        for (int c = 0; c < 64; c++){
            const float* A = act + c*128 + (m0 ^ SW(c));
            float4 a0 = *(const float4*)(A);
            float4 a1 = *(const float4*)(A + 4);
            ulonglong2 b01 = *(const ulonglong2*)(W + c*64);
            ulonglong2 b23 = *(const ulonglong2*)(W + c*64 + 4);
            u64 d0,d1,d2,d3,d4,d5,d6,d7;
            PACK2(d0, a0.x); PACK2(d1, a0.y); PACK2(d2, a0.z); PACK2(d3, a0.w);
            PACK2(d4, a1.x); PACK2(d5, a1.y); PACK2(d6, a1.z); PACK2(d7, a1.w);
            FMA2(acc[ 0], d0, b01.x, acc[ 0]); FMA2(acc[ 1], d0, b01.y, acc[ 1]);
            FMA2(acc[ 2], d0, b23.x, acc[ 2]); FMA2(acc[ 3], d0, b23.y, acc[ 3]);
            FMA2(acc[ 4], d1, b01.x, acc[ 4]); FMA2(acc[ 5], d1, b01.y, acc[ 5]);
            FMA2(acc[ 6], d1, b23.x, acc[ 6]); FMA2(acc[ 7], d1, b23.y, acc[ 7]);
            FMA2(acc[ 8], d2, b01.x, acc[ 8]); FMA2(acc[ 9], d2, b01.y, acc[ 9]);
            FMA2(acc[10], d2, b23.x, acc[10]); FMA2(acc[11], d2, b23.y, acc[11]);
            FMA2(acc[12], d3, b01.x, acc[12]); FMA2(acc[13], d3, b01.y, acc[13]);
            FMA2(acc[14], d3, b23.x, acc[14]); FMA2(acc[15], d3, b23.y, acc[15]);
            FMA2(acc[16], d4, b01.x, acc[16]); FMA2(acc[17], d4, b01.y, acc[17]);
            FMA2(acc[18], d4, b23.x, acc[18]); FMA2(acc[19], d4, b23.y, acc[19]);
            FMA2(acc[20], d5, b01.x, acc[20]); FMA2(acc[21], d5, b01.y, acc[21]);
            FMA2(acc[22], d5, b23.x, acc[22]); FMA2(acc[23], d5, b23.y, acc[23]);
            FMA2(acc[24], d6, b01.x, acc[24]); FMA2(acc[25], d6, b01.y, acc[25]);
            FMA2(acc[26], d6, b23.x, acc[26]); FMA2(acc[27], d6, b23.y, acc[27]);
            FMA2(acc[28], d7, b01.x, acc[28]); FMA2(acc[29], d7, b01.y, acc[29]);
            FMA2(acc[30], d7, b23.x, acc[30]); FMA2(acc[31], d7, b23.y, acc[31]);
        }
    }
    __syncthreads();   // all reads of act complete (part overlaps act)

    // ===== epilogue: relu + masked per-8-row-group partials =====
    {
        float vf[8];
#pragma unroll
        for (int mi = 0; mi < 8; mi++) vf[mi] = validf[m0 + mi];
#pragma unroll
        for (int oj = 0; oj < 4; oj++){
            float slo = 0.f, shi = 0.f;
#pragma unroll
            for (int mi = 0; mi < 8; mi++){
                float lo, hi;
                UNPACK2(lo, hi, acc[mi*4 + oj]);
                slo += fmaxf(lo, 0.f)*vf[mi];
                shi += fmaxf(hi, 0.f)*vf[mi];
            }
            part[mt*64 + o0 + 2*oj    ] = slo;
            part[mt*64 + o0 + 2*oj + 1] = shi;
        }
    }
    __syncthreads();

    // ===== final: 2-group sum + mean + shortcut + relu =====
#pragma unroll
    for (int s = 0; s < 4; s++){
        const int idx = tid + s*128;        // 512 outputs: 8 points x 64 ch
        const int o   = idx >> 3;
        const int pl  = idx & 7;
        const int pt  = pt0 + pl;
        const int p   = pt & (NP-1);
        float sum = part[(pl*2+0)*64 + o] + part[(pl*2+1)*64 + o];
        float denom = fmaxf(vcnt[pl], 1e-8f);
        float res = fmaxf(sum/denom + g_SC[(size_t)pt*64 + o], 0.f);
        out[((size_t)n*64 + o)*NP + p] = res;
    }
}

// ---------------- launch ----------------
extern "C" void kernel_launch(void* const* d_in, const int* in_sizes, int n_in,
                              void* d_out, int out_size)
{
    const float* feats = (const float*)d_in[0];
    const unsigned char* mask = (const unsigned char*)d_in[1];
    const float* W0 = (const float*)d_in[2];
    const float* W1 = (const float*)d_in[3];
    const float* W2 = (const float*)d_in[4];
    const float* Ws = (const float*)d_in[5];

    cudaFuncSetAttribute(edge_kernel, cudaFuncAttributeMaxDynamicSharedMemorySize, SM_TOTAL);

    fold_kernel<<<16, 256>>>(W0, W1, W2, Ws,
        (const float*)d_in[6],  (const float*)d_in[7],  (const float*)d_in[8],  (const float*)d_in[9],
        (const float*)d_in[10], (const float*)d_in[11], (const float*)d_in[12], (const float*)d_in[13],
        (const float*)d_in[14], (const float*)d_in[15], (const float*)d_in[16], (const float*)d_in[17],
        (const float*)d_in[18], (const float*)d_in[19], (const float*)d_in[20], (const float*)d_in[21]);

    knn_kernel<<<NB*128, 256>>>(feats, mask);
    edge_kernel<<<NB*NP/8, 128, SM_TOTAL>>>((float*)d_out);
}